// round 6
// baseline (speedup 1.0000x reference)
#include <cuda_runtime.h>
#include <math.h>
#include <stdint.h>

// ---------------------------------------------------------------------------
// Problem constants
// ---------------------------------------------------------------------------
#define DIMD  1024
#define BATCH 8
#define SEQ   4096
#define MTOT  (BATCH * SEQ)
#define NSCAN 32                  // scan CTAs (fewer agents: less L2 bcast + barrier spread)
#define EPER  (DIMD / NSCAN)      // 32 e-dims per CTA
#define STHREADS 512              // 16 warps; warp w owns k-seg [64w, 64w+64)

// ---------------------------------------------------------------------------
// Scratch (device-global; no allocation allowed)
// ---------------------------------------------------------------------------
__device__ float    g_inp   [(size_t)MTOT * DIMD];
__device__ float    g_gate  [(size_t)MTOT * DIMD];
__device__ float    g_u     [(size_t)MTOT * DIMD];
__device__ float    g_states[(size_t)MTOT * DIMD];
__device__ uint32_t g_sp[2][BATCH * DIMD];   // packed state (bf16 hi | bf16 lo<<16)
__device__ unsigned g_counter;

// ---------------------------------------------------------------------------
// Helpers
// ---------------------------------------------------------------------------
__device__ __forceinline__ uint32_t smem_u32(const void* p) {
    uint32_t a;
    asm("{ .reg .u64 t; cvta.to.shared.u64 t, %1; cvt.u32.u64 %0, t; }" : "=r"(a) : "l"(p));
    return a;
}

#define LDSM4(r, addr)                                                        \
    asm volatile("ldmatrix.sync.aligned.m8n8.x4.shared.b16 {%0,%1,%2,%3}, [%4];" \
        : "=r"((r)[0]), "=r"((r)[1]), "=r"((r)[2]), "=r"((r)[3]) : "r"(addr))

#define MMA16816(d, a, b)                                                     \
    asm volatile("mma.sync.aligned.m16n8k16.row.col.f32.bf16.bf16.f32 "       \
        "{%0,%1,%2,%3}, {%4,%5,%6,%7}, {%8,%9}, {%0,%1,%2,%3};"               \
        : "+f"((d)[0]), "+f"((d)[1]), "+f"((d)[2]), "+f"((d)[3])              \
        : "r"((a)[0]), "r"((a)[1]), "r"((a)[2]), "r"((a)[3]),                 \
          "r"((b)[0]), "r"((b)[1]))

__device__ __forceinline__ uint32_t hipack(float x0, float x1) {
    return __byte_perm(__float_as_uint(x0), __float_as_uint(x1), 0x7632);
}
__device__ __forceinline__ uint32_t lopack(float x0, float x1) {
    float t0 = __uint_as_float(__float_as_uint(x0) & 0xFFFF0000u);
    float t1 = __uint_as_float(__float_as_uint(x1) & 0xFFFF0000u);
    float r0 = x0 - t0, r1 = x1 - t1;
    uint32_t d;
    asm("cvt.rn.bf16x2.f32 %0, %1, %2;" : "=r"(d) : "f"(r1), "f"(r0));
    return d;
}
__device__ __forceinline__ void split8(const float4& a, const float4& b,
                                       uint4& hi, uint4& lo) {
    hi.x = hipack(a.x, a.y); hi.y = hipack(a.z, a.w);
    hi.z = hipack(b.x, b.y); hi.w = hipack(b.z, b.w);
    lo.x = lopack(a.x, a.y); lo.y = lopack(a.z, a.w);
    lo.z = lopack(b.x, b.y); lo.w = lopack(b.z, b.w);
}

__device__ __forceinline__ uint32_t swz(int row, int half) {
    return (uint32_t)(row * 32 + ((half ^ ((row >> 2) & 1)) << 4));
}

__device__ __forceinline__ uint4 ldcg4(const uint4* p) {
    uint4 v;
    asm volatile("ld.global.cg.v4.u32 {%0,%1,%2,%3}, [%4];"
                 : "=r"(v.x), "=r"(v.y), "=r"(v.z), "=r"(v.w) : "l"(p));
    return v;
}

// ---------------------------------------------------------------------------
// Init kernel
// ---------------------------------------------------------------------------
__global__ void init_kernel() {
    int t = blockIdx.x * blockDim.x + threadIdx.x;
    if (t < BATCH * DIMD) { g_sp[0][t] = 0u; g_sp[1][t] = 0u; }
    if (t == 0) g_counter = 0u;
}

// ---------------------------------------------------------------------------
// bf16 3x-split tensor-core GEMM (unchanged, 622us each)
// ---------------------------------------------------------------------------
#define GK 1024
#define GN 1024
#define NCHUNK (GK / 16)

template <int EPI>
__global__ __launch_bounds__(256)
void gemm_mma(const float* __restrict__ X, const float* __restrict__ W,
              const float* __restrict__ bias, float* __restrict__ C)
{
    __shared__ __align__(1024) unsigned char sm[2][4][4096];

    const int tid = threadIdx.x;
    const int wid = tid >> 5, l = tid & 31;
    const int bm = blockIdx.y * 128, bn = blockIdx.x * 128;
    const int wm = wid & 1, wn = wid >> 1;

    const int srow = tid >> 1, shalf = tid & 1;
    const float* Xp = X + (size_t)(bm + srow) * GK + shalf * 8;
    const float* Wp = W + (size_t)(bn + srow) * GK + shalf * 8;
    const uint32_t soff = swz(srow, shalf);

    const int lrow = l & 15, lhalf = l >> 4;
    uint32_t offA[4], offB[2];
#pragma unroll
    for (int mi = 0; mi < 4; mi++) offA[mi] = swz(wm * 64 + mi * 16 + lrow, lhalf);
#pragma unroll
    for (int gi = 0; gi < 2; gi++) offB[gi] = swz(wn * 32 + gi * 16 + lrow, lhalf);

    const uint32_t smbase = smem_u32(&sm[0][0][0]);

    float acc[4][4][4];
#pragma unroll
    for (int mi = 0; mi < 4; mi++)
#pragma unroll
        for (int ni = 0; ni < 4; ni++)
#pragma unroll
            for (int r = 0; r < 4; r++) acc[mi][ni][r] = 0.f;

    {
        float4 a0 = *(const float4*)(Xp + 0), a1 = *(const float4*)(Xp + 4);
        float4 b0 = *(const float4*)(Wp + 0), b1 = *(const float4*)(Wp + 4);
        uint4 hiA, loA, hiB, loB;
        split8(a0, a1, hiA, loA);
        split8(b0, b1, hiB, loB);
        *(uint4*)(&sm[0][0][soff]) = hiA;
        *(uint4*)(&sm[0][1][soff]) = loA;
        *(uint4*)(&sm[0][2][soff]) = hiB;
        *(uint4*)(&sm[0][3][soff]) = loB;
    }
    __syncthreads();

    for (int c = 0; c < NCHUNK; c++) {
        float4 na0, na1, nb0, nb1;
        if (c + 1 < NCHUNK) {
            const int kc = (c + 1) * 16;
            na0 = *(const float4*)(Xp + kc);     na1 = *(const float4*)(Xp + kc + 4);
            nb0 = *(const float4*)(Wp + kc);     nb1 = *(const float4*)(Wp + kc + 4);
        }

        const uint32_t sb = smbase + (uint32_t)(c & 1) * 16384u;

        uint32_t ah[4][4], al[4][4];
#pragma unroll
        for (int mi = 0; mi < 4; mi++) {
            LDSM4(ah[mi], sb + 0 * 4096u + offA[mi]);
            LDSM4(al[mi], sb + 1 * 4096u + offA[mi]);
        }
        uint32_t bh[4][2], bl[4][2];
#pragma unroll
        for (int gi = 0; gi < 2; gi++) {
            uint32_t t[4];
            LDSM4(t, sb + 2 * 4096u + offB[gi]);
            bh[2 * gi + 0][0] = t[0]; bh[2 * gi + 0][1] = t[2];
            bh[2 * gi + 1][0] = t[1]; bh[2 * gi + 1][1] = t[3];
            LDSM4(t, sb + 3 * 4096u + offB[gi]);
            bl[2 * gi + 0][0] = t[0]; bl[2 * gi + 0][1] = t[2];
            bl[2 * gi + 1][0] = t[1]; bl[2 * gi + 1][1] = t[3];
        }

#pragma unroll
        for (int mi = 0; mi < 4; mi++)
#pragma unroll
            for (int ni = 0; ni < 4; ni++)
                MMA16816(acc[mi][ni], ah[mi], bh[ni]);
#pragma unroll
        for (int mi = 0; mi < 4; mi++)
#pragma unroll
            for (int ni = 0; ni < 4; ni++)
                MMA16816(acc[mi][ni], ah[mi], bl[ni]);
#pragma unroll
        for (int mi = 0; mi < 4; mi++)
#pragma unroll
            for (int ni = 0; ni < 4; ni++)
                MMA16816(acc[mi][ni], al[mi], bh[ni]);

        if (c + 1 < NCHUNK) {
            __syncthreads();
            const int s = (c + 1) & 1;
            uint4 hiA, loA, hiB, loB;
            split8(na0, na1, hiA, loA);
            split8(nb0, nb1, hiB, loB);
            *(uint4*)(&sm[s][0][soff]) = hiA;
            *(uint4*)(&sm[s][1][soff]) = loA;
            *(uint4*)(&sm[s][2][soff]) = hiB;
            *(uint4*)(&sm[s][3][soff]) = loB;
            __syncthreads();
        }
    }

    const int erow  = bm + wm * 64 + (l >> 2);
    const int ecol0 = bn + wn * 32 + 2 * (l & 3);

    float2 bv[4];
#pragma unroll
    for (int ni = 0; ni < 4; ni++) {
        if (bias) {
            bv[ni].x = bias[ecol0 + ni * 8];
            bv[ni].y = bias[ecol0 + ni * 8 + 1];
        } else {
            bv[ni].x = 0.f; bv[ni].y = 0.f;
        }
    }

#pragma unroll
    for (int mi = 0; mi < 4; mi++) {
#pragma unroll
        for (int ni = 0; ni < 4; ni++) {
            const int r = erow + mi * 16;
            float2 v0, v1;
            v0.x = acc[mi][ni][0] + bv[ni].x;
            v0.y = acc[mi][ni][1] + bv[ni].y;
            v1.x = acc[mi][ni][2] + bv[ni].x;
            v1.y = acc[mi][ni][3] + bv[ni].y;
            if (EPI == 1) {
                v0.x = 1.f / (1.f + expf(-v0.x));
                v0.y = 1.f / (1.f + expf(-v0.y));
                v1.x = 1.f / (1.f + expf(-v1.x));
                v1.y = 1.f / (1.f + expf(-v1.y));
            }
            *(float2*)(C + (size_t)r * GN + ecol0 + ni * 8)       = v0;
            *(float2*)(C + (size_t)(r + 8) * GN + ecol0 + ni * 8) = v1;
        }
    }
}

// ---------------------------------------------------------------------------
// Grid barrier primitives
// ---------------------------------------------------------------------------
__device__ __forceinline__ void red_release_add1(unsigned* p) {
    asm volatile("red.release.gpu.global.add.u32 [%0], 1;" :: "l"(p) : "memory");
}
__device__ __forceinline__ unsigned ld_acquire(const unsigned* p) {
    unsigned v;
    asm volatile("ld.acquire.gpu.global.u32 %0, [%1];" : "=r"(v) : "l"(p) : "memory");
    return v;
}

// ---------------------------------------------------------------------------
// Tensor-core scan, 32 CTAs x 512 threads (16 warps).
// CTA owns 32 e-dims (4 n-tiles). Warp w owns k-seg [64w, 64w+64) = 4 chunks.
// A-slice stationary in registers (pre-split hi/lo, 64 regs/thread).
// Per step: 1MB chip-wide L2 state bcast (was 4MB), 48 HMMA/warp,
// 16-warp SMEM reduce, 32-agent release/acquire barrier.
// ---------------------------------------------------------------------------
#define SCAN_SMEM (32768 * 2 + 16384)  // SH, SL (16 rows x 2048B), RED 16x256 f32

__global__ __launch_bounds__(STHREADS, 1)
void scan_mma(const float* __restrict__ A)
{
    extern __shared__ unsigned char sms[];
    unsigned char* SH = sms;
    unsigned char* SL = sms + 32768;
    float* RED        = (float*)(sms + 65536);   // [16][256]

    const int tid = threadIdx.x;
    const int w   = tid >> 5;
    const int l   = tid & 31;
    const int eBase = blockIdx.x * EPER;

    const uint32_t shb = smem_u32(SH);
    const uint32_t slb = smem_u32(SL);

    // zero pad rows 8..15 (bytes 16K..32K of each tile)
    for (int i = tid * 16; i < 16384; i += STHREADS * 16) {
        *(uint4*)(SH + 16384 + i) = make_uint4(0, 0, 0, 0);
        *(uint4*)(SL + 16384 + i) = make_uint4(0, 0, 0, 0);
    }

    // --- stationary B fragments: B[k][n] = Amat[e][k], 4 chunks x 4 ntiles
    uint32_t uH[4][4][2], uL[4][4][2];
#pragma unroll
    for (int ni = 0; ni < 4; ni++) {
        const int e_row = eBase + 8 * ni + (l >> 2);
#pragma unroll
        for (int j = 0; j < 4; j++) {
#pragma unroll
            for (int r = 0; r < 2; r++) {
                int k = 64 * w + 16 * j + 2 * (l & 3) + 8 * r;
                float2 av = *(const float2*)(A + (size_t)e_row * DIMD + k);
                uH[j][ni][r] = hipack(av.x, av.y);
                uL[j][ni][r] = lopack(av.x, av.y);
            }
        }
    }

    // --- ldmatrix lane geometry
    const int g    = l >> 3;
    const int lrow = (g & 1) * 8 + (l & 7);
    const int lkh  = (g >> 1) & 1;
    const uint32_t lsw    = (uint32_t)((lrow & 7) << 4);
    const uint32_t cbase  = (uint32_t)(128 * w + 16 * lkh);
    const uint32_t rowoff = (uint32_t)(lrow * 2048);

    // --- state load/unpack mapping: thread t -> batch b = t>>6, 16 words
    const int sb_row = tid >> 6;          // 0..7
    const int sb_it  = tid & 63;          // 16-word group
    const uint32_t ssw = (uint32_t)((sb_row & 7) << 4);
    const uint32_t scb = (uint32_t)(sb_row * 2048 + ((sb_it * 32) ^ ssw));
    const uint32_t scb2 = scb ^ 16u;      // second 16B unit (bit4 flip)

    // --- epilogue mapping (threads 0..255 own one (b,e) output)
    const int b_o = tid >> 5;             // 0..7 for tid<256
    const int e_o = tid & 31;

    float u_r = 0.f, g_r = 0.f, i_r = 0.f;
    if (tid < 256) {
        size_t idx0 = (size_t)b_o * SEQ * DIMD + (size_t)(eBase + e_o);
        u_r = g_u[idx0]; g_r = g_gate[idx0]; i_r = g_inp[idx0];
    }

    __syncthreads();

    for (int t = 0; t < SEQ; t++) {
        // 1) load packed state (L2; .cg to bypass stale L1)
        const uint4* sptr = (const uint4*)(&g_sp[t & 1][sb_row * DIMD + sb_it * 16]);
        uint4 p0 = ldcg4(sptr + 0), p1 = ldcg4(sptr + 1);
        uint4 p2 = ldcg4(sptr + 2), p3 = ldcg4(sptr + 3);

        // 2) unpack to swizzled SMEM tiles
        {
            uint4 h1 = make_uint4(__byte_perm(p0.x, p0.y, 0x5410), __byte_perm(p0.z, p0.w, 0x5410),
                                  __byte_perm(p1.x, p1.y, 0x5410), __byte_perm(p1.z, p1.w, 0x5410));
            uint4 h2 = make_uint4(__byte_perm(p2.x, p2.y, 0x5410), __byte_perm(p2.z, p2.w, 0x5410),
                                  __byte_perm(p3.x, p3.y, 0x5410), __byte_perm(p3.z, p3.w, 0x5410));
            uint4 q1 = make_uint4(__byte_perm(p0.x, p0.y, 0x7632), __byte_perm(p0.z, p0.w, 0x7632),
                                  __byte_perm(p1.x, p1.y, 0x7632), __byte_perm(p1.z, p1.w, 0x7632));
            uint4 q2 = make_uint4(__byte_perm(p2.x, p2.y, 0x7632), __byte_perm(p2.z, p2.w, 0x7632),
                                  __byte_perm(p3.x, p3.y, 0x7632), __byte_perm(p3.z, p3.w, 0x7632));
            *(uint4*)(SH + scb)  = h1;
            *(uint4*)(SH + scb2) = h2;
            *(uint4*)(SL + scb)  = q1;
            *(uint4*)(SL + scb2) = q2;
        }
        __syncthreads();

        // 3) 4 chunks x 4 ntiles x 3 split MMAs
        float acc[4][4];
#pragma unroll
        for (int ni = 0; ni < 4; ni++)
#pragma unroll
            for (int r = 0; r < 4; r++) acc[ni][r] = 0.f;

#pragma unroll
        for (int j = 0; j < 4; j++) {
            uint32_t cb = (cbase + 32u * j) ^ lsw;
            uint32_t ah[4], as[4];
            LDSM4(ah, shb + rowoff + cb);
            LDSM4(as, slb + rowoff + cb);
#pragma unroll
            for (int ni = 0; ni < 4; ni++) {
                MMA16816(acc[ni], ah, uH[j][ni]);
                MMA16816(acc[ni], ah, uL[j][ni]);
                MMA16816(acc[ni], as, uH[j][ni]);
            }
        }

        // 4) stash partials: output o = (l>>2)*32 + 8*ni + 2*(l&3)
        {
            float* rw = RED + w * 256 + (l >> 2) * 32 + 2 * (l & 3);
#pragma unroll
            for (int ni = 0; ni < 4; ni++)
                *(float2*)(rw + 8 * ni) = make_float2(acc[ni][0], acc[ni][1]);
        }
        __syncthreads();

        if (tid < 256) {
            float y = 0.f;
#pragma unroll
            for (int ww = 0; ww < 16; ww++) y += RED[ww * 256 + tid];

            float sv = tanhf(y + u_r);
            sv = g_r * sv + (1.f - g_r) * i_r;

            g_states[((size_t)b_o * SEQ + t) * DIMD + eBase + e_o] = sv;

            uint32_t fui = __float_as_uint(sv);
            float resid = sv - __uint_as_float(fui & 0xFFFF0000u);
            uint32_t lo2;
            asm("cvt.rn.bf16x2.f32 %0, %1, %2;" : "=r"(lo2) : "f"(0.f), "f"(resid));
            uint32_t packed = (fui >> 16) | (lo2 << 16);
            g_sp[(t + 1) & 1][b_o * DIMD + eBase + e_o] = packed;

            if (t + 1 < SEQ) {
                size_t idx = ((size_t)b_o * SEQ + (t + 1)) * DIMD + (eBase + e_o);
                u_r = g_u[idx]; g_r = g_gate[idx]; i_r = g_inp[idx];
            }
        }

        // 5) grid barrier (32 agents)
        __syncthreads();
        if (tid == 0) {
            red_release_add1(&g_counter);
            const unsigned target = (unsigned)NSCAN * (unsigned)(t + 1);
            while (ld_acquire(&g_counter) < target) { }
        }
        __syncthreads();
    }
}

// ---------------------------------------------------------------------------
// kernel_launch
// ---------------------------------------------------------------------------
extern "C" void kernel_launch(void* const* d_in, const int* in_sizes, int n_in,
                              void* d_out, int out_size)
{
    (void)in_sizes; (void)n_in; (void)out_size;

    const float* x      = (const float*)d_in[0];
    const float* A      = (const float*)d_in[1];
    const float* Bmat   = (const float*)d_in[2];
    const float* W_in   = (const float*)d_in[3];
    const float* b_in   = (const float*)d_in[4];
    const float* W_gate = (const float*)d_in[5];
    const float* b_gate = (const float*)d_in[6];
    const float* W_out  = (const float*)d_in[7];
    const float* b_out  = (const float*)d_in[8];
    float* out          = (float*)d_out;

    void *p_inp, *p_gate, *p_u, *p_states;
    cudaGetSymbolAddress(&p_inp,    g_inp);
    cudaGetSymbolAddress(&p_gate,   g_gate);
    cudaGetSymbolAddress(&p_u,      g_u);
    cudaGetSymbolAddress(&p_states, g_states);

    float* inp    = (float*)p_inp;
    float* gate   = (float*)p_gate;
    float* u      = (float*)p_u;
    float* states = (float*)p_states;

    cudaFuncSetAttribute(scan_mma, cudaFuncAttributeMaxDynamicSharedMemorySize, SCAN_SMEM);

    init_kernel<<<(BATCH * DIMD + 255) / 256, 256>>>();

    dim3 gg(DIMD / 128, MTOT / 128);   // (8, 256)

    gemm_mma<0><<<gg, 256>>>(x, W_in, b_in, inp);
    gemm_mma<1><<<gg, 256>>>(inp, W_gate, b_gate, gate);
    gemm_mma<0><<<gg, 256>>>(inp, Bmat, nullptr, u);
    scan_mma<<<NSCAN, STHREADS, SCAN_SMEM>>>(A);
    gemm_mma<0><<<gg, 256>>>(states, W_out, b_out, out);
}

// round 7
// speedup vs baseline: 1.0226x; 1.0226x over previous
#include <cuda_runtime.h>
#include <math.h>
#include <stdint.h>

// ---------------------------------------------------------------------------
// Problem constants
// ---------------------------------------------------------------------------
#define DIMD  1024
#define BATCH 8
#define SEQ   4096
#define MTOT  (BATCH * SEQ)
#define NSCAN 128
#define EPER  (DIMD / NSCAN)   // 8 e-dims per CTA

// ---------------------------------------------------------------------------
// Scratch (device-global; no allocation allowed)
// ---------------------------------------------------------------------------
__device__ float    g_inp   [(size_t)MTOT * DIMD];
__device__ float    g_gate  [(size_t)MTOT * DIMD];
__device__ float    g_u     [(size_t)MTOT * DIMD];
__device__ float    g_states[(size_t)MTOT * DIMD];
__device__ uint32_t g_spA[2][4 * DIMD];     // batches 0-3, packed (bf16hi | bf16lo<<16)
__device__ uint32_t g_spB[2][4 * DIMD];     // batches 4-7
__device__ unsigned g_flagA[NSCAN * 32];    // per-CTA flags, 128B apart
__device__ unsigned g_flagB[NSCAN * 32];

// ---------------------------------------------------------------------------
// Helpers
// ---------------------------------------------------------------------------
__device__ __forceinline__ uint32_t smem_u32(const void* p) {
    uint32_t a;
    asm("{ .reg .u64 t; cvta.to.shared.u64 t, %1; cvt.u32.u64 %0, t; }" : "=r"(a) : "l"(p));
    return a;
}

#define LDSM4(r, addr)                                                        \
    asm volatile("ldmatrix.sync.aligned.m8n8.x4.shared.b16 {%0,%1,%2,%3}, [%4];" \
        : "=r"((r)[0]), "=r"((r)[1]), "=r"((r)[2]), "=r"((r)[3]) : "r"(addr))

#define LDSM2(r0, r1, addr)                                                   \
    asm volatile("ldmatrix.sync.aligned.m8n8.x2.shared.b16 {%0,%1}, [%2];"    \
        : "=r"(r0), "=r"(r1) : "r"(addr))

#define MMA16816(d, a, b)                                                     \
    asm volatile("mma.sync.aligned.m16n8k16.row.col.f32.bf16.bf16.f32 "       \
        "{%0,%1,%2,%3}, {%4,%5,%6,%7}, {%8,%9}, {%0,%1,%2,%3};"               \
        : "+f"((d)[0]), "+f"((d)[1]), "+f"((d)[2]), "+f"((d)[3])              \
        : "r"((a)[0]), "r"((a)[1]), "r"((a)[2]), "r"((a)[3]),                 \
          "r"((b)[0]), "r"((b)[1]))

// A-operand rows 8-15 are structurally zero -> a1 = a3 = 0
#define MMAZ(d, a0v, a2v, b)                                                  \
    asm volatile("mma.sync.aligned.m16n8k16.row.col.f32.bf16.bf16.f32 "       \
        "{%0,%1,%2,%3}, {%4,%5,%6,%7}, {%8,%9}, {%0,%1,%2,%3};"               \
        : "+f"((d)[0]), "+f"((d)[1]), "+f"((d)[2]), "+f"((d)[3])              \
        : "r"(a0v), "r"(0u), "r"(a2v), "r"(0u),                               \
          "r"((b)[0]), "r"((b)[1]))

__device__ __forceinline__ uint32_t hipack(float x0, float x1) {
    return __byte_perm(__float_as_uint(x0), __float_as_uint(x1), 0x7632);
}
__device__ __forceinline__ uint32_t lopack(float x0, float x1) {
    float t0 = __uint_as_float(__float_as_uint(x0) & 0xFFFF0000u);
    float t1 = __uint_as_float(__float_as_uint(x1) & 0xFFFF0000u);
    float r0 = x0 - t0, r1 = x1 - t1;
    uint32_t d;
    asm("cvt.rn.bf16x2.f32 %0, %1, %2;" : "=r"(d) : "f"(r1), "f"(r0));
    return d;
}
__device__ __forceinline__ void split8(const float4& a, const float4& b,
                                       uint4& hi, uint4& lo) {
    hi.x = hipack(a.x, a.y); hi.y = hipack(a.z, a.w);
    hi.z = hipack(b.x, b.y); hi.w = hipack(b.z, b.w);
    lo.x = lopack(a.x, a.y); lo.y = lopack(a.z, a.w);
    lo.z = lopack(b.x, b.y); lo.w = lopack(b.z, b.w);
}

__device__ __forceinline__ uint32_t swz(int row, int half) {
    return (uint32_t)(row * 32 + ((half ^ ((row >> 2) & 1)) << 4));
}

__device__ __forceinline__ uint4 ldcg4(const uint4* p) {
    uint4 v;
    asm volatile("ld.global.cg.v4.u32 {%0,%1,%2,%3}, [%4];"
                 : "=r"(v.x), "=r"(v.y), "=r"(v.z), "=r"(v.w) : "l"(p));
    return v;
}
__device__ __forceinline__ void st_release(unsigned* p, unsigned v) {
    asm volatile("st.release.gpu.global.u32 [%0], %1;" :: "l"(p), "r"(v) : "memory");
}
__device__ __forceinline__ unsigned ld_acquire(const unsigned* p) {
    unsigned v;
    asm volatile("ld.acquire.gpu.global.u32 %0, [%1];" : "=r"(v) : "l"(p) : "memory");
    return v;
}
__device__ __forceinline__ void barx(int id) {
    asm volatile("bar.sync %0, 128;" :: "r"(id) : "memory");
}

// ---------------------------------------------------------------------------
// Init kernel: zero state buffers + flags (graph replay determinism)
// ---------------------------------------------------------------------------
__global__ void init_kernel() {
    int t = blockIdx.x * blockDim.x + threadIdx.x;
    if (t < 4 * DIMD) {
        g_spA[0][t] = 0u; g_spA[1][t] = 0u;
        g_spB[0][t] = 0u; g_spB[1][t] = 0u;
        g_flagA[t] = 0u;  g_flagB[t] = 0u;   // 4096 == NSCAN*32
    }
}

// ---------------------------------------------------------------------------
// bf16 3x-split tensor-core GEMM (unchanged, 622us each)
// ---------------------------------------------------------------------------
#define GK 1024
#define GN 1024
#define NCHUNK (GK / 16)

template <int EPI>
__global__ __launch_bounds__(256)
void gemm_mma(const float* __restrict__ X, const float* __restrict__ W,
              const float* __restrict__ bias, float* __restrict__ C)
{
    __shared__ __align__(1024) unsigned char sm[2][4][4096];

    const int tid = threadIdx.x;
    const int wid = tid >> 5, l = tid & 31;
    const int bm = blockIdx.y * 128, bn = blockIdx.x * 128;
    const int wm = wid & 1, wn = wid >> 1;

    const int srow = tid >> 1, shalf = tid & 1;
    const float* Xp = X + (size_t)(bm + srow) * GK + shalf * 8;
    const float* Wp = W + (size_t)(bn + srow) * GK + shalf * 8;
    const uint32_t soff = swz(srow, shalf);

    const int lrow = l & 15, lhalf = l >> 4;
    uint32_t offA[4], offB[2];
#pragma unroll
    for (int mi = 0; mi < 4; mi++) offA[mi] = swz(wm * 64 + mi * 16 + lrow, lhalf);
#pragma unroll
    for (int gi = 0; gi < 2; gi++) offB[gi] = swz(wn * 32 + gi * 16 + lrow, lhalf);

    const uint32_t smbase = smem_u32(&sm[0][0][0]);

    float acc[4][4][4];
#pragma unroll
    for (int mi = 0; mi < 4; mi++)
#pragma unroll
        for (int ni = 0; ni < 4; ni++)
#pragma unroll
            for (int r = 0; r < 4; r++) acc[mi][ni][r] = 0.f;

    {
        float4 a0 = *(const float4*)(Xp + 0), a1 = *(const float4*)(Xp + 4);
        float4 b0 = *(const float4*)(Wp + 0), b1 = *(const float4*)(Wp + 4);
        uint4 hiA, loA, hiB, loB;
        split8(a0, a1, hiA, loA);
        split8(b0, b1, hiB, loB);
        *(uint4*)(&sm[0][0][soff]) = hiA;
        *(uint4*)(&sm[0][1][soff]) = loA;
        *(uint4*)(&sm[0][2][soff]) = hiB;
        *(uint4*)(&sm[0][3][soff]) = loB;
    }
    __syncthreads();

    for (int c = 0; c < NCHUNK; c++) {
        float4 na0, na1, nb0, nb1;
        if (c + 1 < NCHUNK) {
            const int kc = (c + 1) * 16;
            na0 = *(const float4*)(Xp + kc);     na1 = *(const float4*)(Xp + kc + 4);
            nb0 = *(const float4*)(Wp + kc);     nb1 = *(const float4*)(Wp + kc + 4);
        }

        const uint32_t sb = smbase + (uint32_t)(c & 1) * 16384u;

        uint32_t ah[4][4], al[4][4];
#pragma unroll
        for (int mi = 0; mi < 4; mi++) {
            LDSM4(ah[mi], sb + 0 * 4096u + offA[mi]);
            LDSM4(al[mi], sb + 1 * 4096u + offA[mi]);
        }
        uint32_t bh[4][2], bl[4][2];
#pragma unroll
        for (int gi = 0; gi < 2; gi++) {
            uint32_t t[4];
            LDSM4(t, sb + 2 * 4096u + offB[gi]);
            bh[2 * gi + 0][0] = t[0]; bh[2 * gi + 0][1] = t[2];
            bh[2 * gi + 1][0] = t[1]; bh[2 * gi + 1][1] = t[3];
            LDSM4(t, sb + 3 * 4096u + offB[gi]);
            bl[2 * gi + 0][0] = t[0]; bl[2 * gi + 0][1] = t[2];
            bl[2 * gi + 1][0] = t[1]; bl[2 * gi + 1][1] = t[3];
        }

#pragma unroll
        for (int mi = 0; mi < 4; mi++)
#pragma unroll
            for (int ni = 0; ni < 4; ni++)
                MMA16816(acc[mi][ni], ah[mi], bh[ni]);
#pragma unroll
        for (int mi = 0; mi < 4; mi++)
#pragma unroll
            for (int ni = 0; ni < 4; ni++)
                MMA16816(acc[mi][ni], ah[mi], bl[ni]);
#pragma unroll
        for (int mi = 0; mi < 4; mi++)
#pragma unroll
            for (int ni = 0; ni < 4; ni++)
                MMA16816(acc[mi][ni], al[mi], bh[ni]);

        if (c + 1 < NCHUNK) {
            __syncthreads();
            const int s = (c + 1) & 1;
            uint4 hiA, loA, hiB, loB;
            split8(na0, na1, hiA, loA);
            split8(nb0, nb1, hiB, loB);
            *(uint4*)(&sm[s][0][soff]) = hiA;
            *(uint4*)(&sm[s][1][soff]) = loA;
            *(uint4*)(&sm[s][2][soff]) = hiB;
            *(uint4*)(&sm[s][3][soff]) = loB;
            __syncthreads();
        }
    }

    const int erow  = bm + wm * 64 + (l >> 2);
    const int ecol0 = bn + wn * 32 + 2 * (l & 3);

    float2 bv[4];
#pragma unroll
    for (int ni = 0; ni < 4; ni++) {
        if (bias) {
            bv[ni].x = bias[ecol0 + ni * 8];
            bv[ni].y = bias[ecol0 + ni * 8 + 1];
        } else {
            bv[ni].x = 0.f; bv[ni].y = 0.f;
        }
    }

#pragma unroll
    for (int mi = 0; mi < 4; mi++) {
#pragma unroll
        for (int ni = 0; ni < 4; ni++) {
            const int r = erow + mi * 16;
            float2 v0, v1;
            v0.x = acc[mi][ni][0] + bv[ni].x;
            v0.y = acc[mi][ni][1] + bv[ni].y;
            v1.x = acc[mi][ni][2] + bv[ni].x;
            v1.y = acc[mi][ni][3] + bv[ni].y;
            if (EPI == 1) {
                v0.x = 1.f / (1.f + expf(-v0.x));
                v0.y = 1.f / (1.f + expf(-v0.y));
                v1.x = 1.f / (1.f + expf(-v1.x));
                v1.y = 1.f / (1.f + expf(-v1.y));
            }
            *(float2*)(C + (size_t)r * GN + ecol0 + ni * 8)       = v0;
            *(float2*)(C + (size_t)(r + 8) * GN + ecol0 + ni * 8) = v1;
        }
    }
}

// ---------------------------------------------------------------------------
// Warp-specialized two-phase scan.
// 128 CTAs x 256 threads. Warps 0-3 = group A (batches 0-3), warps 4-7 =
// group B (batches 4-7). Each group runs an independent recurrence chain
// with its own state buffers, flag array, SMEM tiles, and named barrier.
// The two chains interleave on the SMSPs, hiding each other's latency.
// Per group-step: 96 parallel flag polls -> LDG packed state (4 rows x 4KB)
// -> unpack to swizzled SMEM -> ldmatrix.x2 + 3-split MMA (warp = 256 k)
// -> 4-warp SMEM reduce -> epi warp: tanh/gate, STG state+flag(st.release).
// ---------------------------------------------------------------------------
#define SCAN_SMEM (2 * 32768 + 1024)   // [A: hi 16K, lo 16K][B: ...][RED A/B 512 each]

__global__ __launch_bounds__(256, 1)
void scan_ws(const float* __restrict__ A)
{
    extern __shared__ unsigned char sms[];

    const int tid = threadIdx.x;
    const int g   = tid >> 7;           // group 0 (warps 0-3) / 1 (warps 4-7)
    const int gt  = tid & 127;          // thread-in-group
    const int wl  = gt >> 5;            // warp-in-group 0-3
    const int l   = tid & 31;
    const int bid = blockIdx.x;
    const int eBase = bid * EPER;
    const int barid = 1 + g;

    unsigned char* SH = sms + g * 32768;
    unsigned char* SL = SH + 16384;
    float* RED        = (float*)(sms + 65536 + g * 512);   // [4][32]
    const uint32_t shb = smem_u32(SH);
    const uint32_t slb = smem_u32(SL);

    uint32_t* const stb0 = g ? g_spB[0] : g_spA[0];
    uint32_t* const stb1 = g ? g_spB[1] : g_spA[1];
    unsigned* const flags = g ? g_flagB : g_flagA;

    // zero rows 4-7 of all 4 tiles once (A rows of the m16 fragment 8-15 come
    // from MMAZ zeros; rows 4-7 of the 8-row tile hold batch pad = 0)
    for (int i = tid * 16; i < 32768; i += 256 * 16) {
        int tile = i >> 13, off = i & 8191;
        *(uint4*)(sms + tile * 16384 + 8192 + off) = make_uint4(0, 0, 0, 0);
    }

    // --- stationary B fragments: warp covers k in [256*wl, 256*wl+256)
    uint32_t uH[16][2], uL[16][2];
    {
        const int e_row = eBase + (l >> 2);
#pragma unroll
        for (int j = 0; j < 16; j++) {
#pragma unroll
            for (int r = 0; r < 2; r++) {
                int k = 256 * wl + 16 * j + 2 * (l & 3) + 8 * r;
                float2 av = *(const float2*)(A + (size_t)e_row * DIMD + k);
                uH[j][r] = hipack(av.x, av.y);
                uL[j][r] = lopack(av.x, av.y);
            }
        }
    }

    // --- ldmatrix.x2 lane geometry: r = lane&7 row, sel = k-half
    const int lr  = l & 7;
    const int sel = (l >> 3) & 1;
    const uint32_t lrow_off = (uint32_t)(lr * 2048);
    const uint32_t lxr      = (uint32_t)(lr << 4);

    // --- poll assignment: threads gt in [32,128) poll flags
    const unsigned* pollp1 = nullptr;
    const unsigned* pollp2 = nullptr;
    if (gt >= 32) {
        int c1 = gt - 32;                       // 0..95
        pollp1 = &flags[c1 * 32];
        pollp2 = (c1 < 32) ? &flags[(96 + c1) * 32] : pollp1;
    }

    // --- epilogue mapping (warp 0 of group): lane -> (b_loc, e)
    const int b_loc = gt >> 3;                  // valid for gt<32
    const int e_o   = gt & 7;
    const int b_glb = 4 * g + b_loc;

    float u_r = 0.f, g_r = 0.f, i_r = 0.f;
    if (gt < 32) {
        size_t idx0 = (size_t)b_glb * SEQ * DIMD + (size_t)(eBase + e_o);
        u_r = g_u[idx0]; g_r = g_gate[idx0]; i_r = g_inp[idx0];
    }

    __syncthreads();   // zero-fill visible to both groups

    for (int t = 0; t < SEQ; t++) {
        // 1) wait for all producers of this group's state(t)
        if (gt >= 32) {
            const unsigned ut = (unsigned)t;
            while (ld_acquire(pollp1) < ut) { }
            while (ld_acquire(pollp2) < ut) { }
        }
        barx(barid);   // S0: state(t) globally visible; epi warp rejoined

        // 2) load packed state row (warp wl <-> batch row wl), stage to SMEM
        {
            const uint32_t* sb = ((t & 1) ? stb1 : stb0) + wl * 1024;
            uint4 p[4][2];
#pragma unroll
            for (int ui = 0; ui < 4; ui++) {
                int u = l + 32 * ui;
                p[ui][0] = ldcg4((const uint4*)(sb + 8 * u));
                p[ui][1] = ldcg4((const uint4*)(sb + 8 * u + 4));
            }
#pragma unroll
            for (int ui = 0; ui < 4; ui++) {
                int u = l + 32 * ui;
                uint4 hi, lo;
                hi.x = __byte_perm(p[ui][0].x, p[ui][0].y, 0x5410);
                hi.y = __byte_perm(p[ui][0].z, p[ui][0].w, 0x5410);
                hi.z = __byte_perm(p[ui][1].x, p[ui][1].y, 0x5410);
                hi.w = __byte_perm(p[ui][1].z, p[ui][1].w, 0x5410);
                lo.x = __byte_perm(p[ui][0].x, p[ui][0].y, 0x7632);
                lo.y = __byte_perm(p[ui][0].z, p[ui][0].w, 0x7632);
                lo.z = __byte_perm(p[ui][1].x, p[ui][1].y, 0x7632);
                lo.w = __byte_perm(p[ui][1].z, p[ui][1].w, 0x7632);
                uint32_t off = (uint32_t)(wl * 2048) + (((uint32_t)u << 4) ^ ((uint32_t)wl << 4));
                *(uint4*)(SH + off) = hi;
                *(uint4*)(SL + off) = lo;
            }
        }
        barx(barid);   // S1: tiles staged

        // 3) 16 chunks x 3 split MMAs (a1=a3=0: batch rows 8-15 don't exist)
        float acc[4] = {0.f, 0.f, 0.f, 0.f};
#pragma unroll
        for (int j = 0; j < 16; j++) {
            uint32_t ub = (uint32_t)(32 * wl + 2 * j + sel);
            uint32_t cb = lrow_off + ((ub << 4) ^ lxr);
            uint32_t h0, h1, s0, s1;
            LDSM2(h0, h1, shb + cb);
            LDSM2(s0, s1, slb + cb);
            MMAZ(acc, h0, h1, uH[j]);
            MMAZ(acc, h0, h1, uL[j]);
            MMAZ(acc, s0, s1, uH[j]);
        }

        // 4) partials: lanes 0-15 hold valid rows (b = l>>2 in 0..3)
        if (l < 16)
            *(float2*)&RED[wl * 32 + (l >> 2) * 8 + 2 * (l & 3)] =
                make_float2(acc[0], acc[1]);
        barx(barid);   // S2: partials visible

        // 5) epilogue: warp 0 of group (32 outputs)
        if (gt < 32) {
            float y = RED[gt] + RED[32 + gt] + RED[64 + gt] + RED[96 + gt];

            float sv = tanhf(y + u_r);
            sv = g_r * sv + (1.f - g_r) * i_r;

            g_states[((size_t)b_glb * SEQ + t) * DIMD + eBase + e_o] = sv;

            uint32_t fui = __float_as_uint(sv);
            float resid = sv - __uint_as_float(fui & 0xFFFF0000u);
            uint32_t lo2;
            asm("cvt.rn.bf16x2.f32 %0, %1, %2;" : "=r"(lo2) : "f"(0.f), "f"(resid));
            uint32_t packed = (fui >> 16) | (lo2 << 16);
            ((t & 1) ? stb0 : stb1)[b_loc * DIMD + eBase + e_o] = packed;

            if (t + 1 < SEQ) {
                size_t idx = ((size_t)b_glb * SEQ + (t + 1)) * DIMD + (eBase + e_o);
                u_r = g_u[idx]; g_r = g_gate[idx]; i_r = g_inp[idx];
            }
            __syncwarp();
            if (gt == 0) st_release(&flags[bid * 32], (unsigned)(t + 1));
        }
        // no group barrier here: warps 1-3 run ahead to the next poll,
        // warp 0 rejoins at S0.
    }
}

// ---------------------------------------------------------------------------
// kernel_launch
// ---------------------------------------------------------------------------
extern "C" void kernel_launch(void* const* d_in, const int* in_sizes, int n_in,
                              void* d_out, int out_size)
{
    (void)in_sizes; (void)n_in; (void)out_size;

    const float* x      = (const float*)d_in[0];
    const float* A      = (const float*)d_in[1];
    const float* Bmat   = (const float*)d_in[2];
    const float* W_in   = (const float*)d_in[3];
    const float* b_in   = (const float*)d_in[4];
    const float* W_gate = (const float*)d_in[5];
    const float* b_gate = (const float*)d_in[6];
    const float* W_out  = (const float*)d_in[7];
    const float* b_out  = (const float*)d_in[8];
    float* out          = (float*)d_out;

    void *p_inp, *p_gate, *p_u, *p_states;
    cudaGetSymbolAddress(&p_inp,    g_inp);
    cudaGetSymbolAddress(&p_gate,   g_gate);
    cudaGetSymbolAddress(&p_u,      g_u);
    cudaGetSymbolAddress(&p_states, g_states);

    float* inp    = (float*)p_inp;
    float* gate   = (float*)p_gate;
    float* u      = (float*)p_u;
    float* states = (float*)p_states;

    cudaFuncSetAttribute(scan_ws, cudaFuncAttributeMaxDynamicSharedMemorySize, SCAN_SMEM);

    init_kernel<<<(4 * DIMD + 255) / 256, 256>>>();

    dim3 gg(DIMD / 128, MTOT / 128);   // (8, 256)

    gemm_mma<0><<<gg, 256>>>(x, W_in, b_in, inp);
    gemm_mma<1><<<gg, 256>>>(inp, W_gate, b_gate, gate);
    gemm_mma<0><<<gg, 256>>>(inp, Bmat, nullptr, u);
    scan_ws<<<NSCAN, 256, SCAN_SMEM>>>(A);
    gemm_mma<0><<<gg, 256>>>(states, W_out, b_out, out);
}

// round 8
// speedup vs baseline: 1.1011x; 1.0767x over previous
#include <cuda_runtime.h>
#include <math.h>
#include <stdint.h>

// ---------------------------------------------------------------------------
// Problem constants
// ---------------------------------------------------------------------------
#define DIMD  1024
#define BATCH 8
#define SEQ   4096
#define MTOT  (BATCH * SEQ)
#define NSCAN 128
#define EPER  (DIMD / NSCAN)   // 8 e-dims per CTA

// ---------------------------------------------------------------------------
// Scratch (device-global; no allocation allowed)
// ---------------------------------------------------------------------------
__device__ float    g_inp   [(size_t)MTOT * DIMD];
__device__ float    g_gate  [(size_t)MTOT * DIMD];
__device__ float    g_u     [(size_t)MTOT * DIMD];
__device__ float    g_states[(size_t)MTOT * DIMD];
// state in MMA-fragment layout: word W = j*64 + b*8 + c*2 + h
//   j = k-chunk (k16), b = batch row, c = k-pair-in-half, h = k-half (0:k<8)
// word = bf16x2 of state dims (e) {16j+8h+2c, 16j+8h+2c+1}
__device__ uint32_t g_fh[2][64 * 64];   // hi split, ping-pong
__device__ uint32_t g_fl[2][64 * 64];   // lo split, ping-pong
__device__ unsigned g_counter;

// ---------------------------------------------------------------------------
// Helpers
// ---------------------------------------------------------------------------
__device__ __forceinline__ uint32_t smem_u32(const void* p) {
    uint32_t a;
    asm("{ .reg .u64 t; cvta.to.shared.u64 t, %1; cvt.u32.u64 %0, t; }" : "=r"(a) : "l"(p));
    return a;
}

#define LDSM4(r, addr)                                                        \
    asm volatile("ldmatrix.sync.aligned.m8n8.x4.shared.b16 {%0,%1,%2,%3}, [%4];" \
        : "=r"((r)[0]), "=r"((r)[1]), "=r"((r)[2]), "=r"((r)[3]) : "r"(addr))

#define MMA16816(d, a, b)                                                     \
    asm volatile("mma.sync.aligned.m16n8k16.row.col.f32.bf16.bf16.f32 "       \
        "{%0,%1,%2,%3}, {%4,%5,%6,%7}, {%8,%9}, {%0,%1,%2,%3};"               \
        : "+f"((d)[0]), "+f"((d)[1]), "+f"((d)[2]), "+f"((d)[3])              \
        : "r"((a)[0]), "r"((a)[1]), "r"((a)[2]), "r"((a)[3]),                 \
          "r"((b)[0]), "r"((b)[1]))

// A rows 8-15 structurally zero -> a1 = a3 = 0
#define MMAZ(d, a0v, a2v, b)                                                  \
    asm volatile("mma.sync.aligned.m16n8k16.row.col.f32.bf16.bf16.f32 "       \
        "{%0,%1,%2,%3}, {%4,%5,%6,%7}, {%8,%9}, {%0,%1,%2,%3};"               \
        : "+f"((d)[0]), "+f"((d)[1]), "+f"((d)[2]), "+f"((d)[3])              \
        : "r"(a0v), "r"(0u), "r"(a2v), "r"(0u),                               \
          "r"((b)[0]), "r"((b)[1]))

__device__ __forceinline__ uint32_t hipack(float x0, float x1) {
    return __byte_perm(__float_as_uint(x0), __float_as_uint(x1), 0x7632);
}
__device__ __forceinline__ uint32_t lopack(float x0, float x1) {
    float t0 = __uint_as_float(__float_as_uint(x0) & 0xFFFF0000u);
    float t1 = __uint_as_float(__float_as_uint(x1) & 0xFFFF0000u);
    float r0 = x0 - t0, r1 = x1 - t1;
    uint32_t d;
    asm("cvt.rn.bf16x2.f32 %0, %1, %2;" : "=r"(d) : "f"(r1), "f"(r0));
    return d;
}
__device__ __forceinline__ void split8(const float4& a, const float4& b,
                                       uint4& hi, uint4& lo) {
    hi.x = hipack(a.x, a.y); hi.y = hipack(a.z, a.w);
    hi.z = hipack(b.x, b.y); hi.w = hipack(b.z, b.w);
    lo.x = lopack(a.x, a.y); lo.y = lopack(a.z, a.w);
    lo.z = lopack(b.x, b.y); lo.w = lopack(b.z, b.w);
}

__device__ __forceinline__ uint32_t swz(int row, int half) {
    return (uint32_t)(row * 32 + ((half ^ ((row >> 2) & 1)) << 4));
}

__device__ __forceinline__ uint2 ldcg2(const uint32_t* p) {
    uint2 v;
    asm volatile("ld.global.cg.v2.u32 {%0,%1}, [%2];" : "=r"(v.x), "=r"(v.y) : "l"(p));
    return v;
}
__device__ __forceinline__ void red_release_add1(unsigned* p) {
    asm volatile("red.release.gpu.global.add.u32 [%0], 1;" :: "l"(p) : "memory");
}
__device__ __forceinline__ unsigned ld_acquire(const unsigned* p) {
    unsigned v;
    asm volatile("ld.acquire.gpu.global.u32 %0, [%1];" : "=r"(v) : "l"(p) : "memory");
    return v;
}

// ---------------------------------------------------------------------------
// Init kernel: zero fragment state buffers + counter
// ---------------------------------------------------------------------------
__global__ void init_kernel() {
    int t = blockIdx.x * blockDim.x + threadIdx.x;
    if (t < 64 * 64) {
        g_fh[0][t] = 0u; g_fh[1][t] = 0u;
        g_fl[0][t] = 0u; g_fl[1][t] = 0u;
    }
    if (t == 0) g_counter = 0u;
}

// ---------------------------------------------------------------------------
// bf16 3x-split tensor-core GEMM (R4 kernel; occupancy 2 CTAs/SM)
// ---------------------------------------------------------------------------
#define GK 1024
#define GN 1024
#define NCHUNK (GK / 16)

template <int EPI>
__global__ __launch_bounds__(256, 2)
void gemm_mma(const float* __restrict__ X, const float* __restrict__ W,
              const float* __restrict__ bias, float* __restrict__ C)
{
    __shared__ __align__(1024) unsigned char sm[2][4][4096];

    const int tid = threadIdx.x;
    const int wid = tid >> 5, l = tid & 31;
    const int bm = blockIdx.y * 128, bn = blockIdx.x * 128;
    const int wm = wid & 1, wn = wid >> 1;

    const int srow = tid >> 1, shalf = tid & 1;
    const float* Xp = X + (size_t)(bm + srow) * GK + shalf * 8;
    const float* Wp = W + (size_t)(bn + srow) * GK + shalf * 8;
    const uint32_t soff = swz(srow, shalf);

    const int lrow = l & 15, lhalf = l >> 4;
    uint32_t offA[4], offB[2];
#pragma unroll
    for (int mi = 0; mi < 4; mi++) offA[mi] = swz(wm * 64 + mi * 16 + lrow, lhalf);
#pragma unroll
    for (int gi = 0; gi < 2; gi++) offB[gi] = swz(wn * 32 + gi * 16 + lrow, lhalf);

    const uint32_t smbase = smem_u32(&sm[0][0][0]);

    float acc[4][4][4];
#pragma unroll
    for (int mi = 0; mi < 4; mi++)
#pragma unroll
        for (int ni = 0; ni < 4; ni++)
#pragma unroll
            for (int r = 0; r < 4; r++) acc[mi][ni][r] = 0.f;

    {
        float4 a0 = *(const float4*)(Xp + 0), a1 = *(const float4*)(Xp + 4);
        float4 b0 = *(const float4*)(Wp + 0), b1 = *(const float4*)(Wp + 4);
        uint4 hiA, loA, hiB, loB;
        split8(a0, a1, hiA, loA);
        split8(b0, b1, hiB, loB);
        *(uint4*)(&sm[0][0][soff]) = hiA;
        *(uint4*)(&sm[0][1][soff]) = loA;
        *(uint4*)(&sm[0][2][soff]) = hiB;
        *(uint4*)(&sm[0][3][soff]) = loB;
    }
    __syncthreads();

    for (int c = 0; c < NCHUNK; c++) {
        float4 na0, na1, nb0, nb1;
        if (c + 1 < NCHUNK) {
            const int kc = (c + 1) * 16;
            na0 = *(const float4*)(Xp + kc);     na1 = *(const float4*)(Xp + kc + 4);
            nb0 = *(const float4*)(Wp + kc);     nb1 = *(const float4*)(Wp + kc + 4);
        }

        const uint32_t sb = smbase + (uint32_t)(c & 1) * 16384u;

        uint32_t ah[4][4], al[4][4];
#pragma unroll
        for (int mi = 0; mi < 4; mi++) {
            LDSM4(ah[mi], sb + 0 * 4096u + offA[mi]);
            LDSM4(al[mi], sb + 1 * 4096u + offA[mi]);
        }
        uint32_t bh[4][2], bl[4][2];
#pragma unroll
        for (int gi = 0; gi < 2; gi++) {
            uint32_t t[4];
            LDSM4(t, sb + 2 * 4096u + offB[gi]);
            bh[2 * gi + 0][0] = t[0]; bh[2 * gi + 0][1] = t[2];
            bh[2 * gi + 1][0] = t[1]; bh[2 * gi + 1][1] = t[3];
            LDSM4(t, sb + 3 * 4096u + offB[gi]);
            bl[2 * gi + 0][0] = t[0]; bl[2 * gi + 0][1] = t[2];
            bl[2 * gi + 1][0] = t[1]; bl[2 * gi + 1][1] = t[3];
        }

#pragma unroll
        for (int mi = 0; mi < 4; mi++)
#pragma unroll
            for (int ni = 0; ni < 4; ni++)
                MMA16816(acc[mi][ni], ah[mi], bh[ni]);
#pragma unroll
        for (int mi = 0; mi < 4; mi++)
#pragma unroll
            for (int ni = 0; ni < 4; ni++)
                MMA16816(acc[mi][ni], ah[mi], bl[ni]);
#pragma unroll
        for (int mi = 0; mi < 4; mi++)
#pragma unroll
            for (int ni = 0; ni < 4; ni++)
                MMA16816(acc[mi][ni], al[mi], bh[ni]);

        if (c + 1 < NCHUNK) {
            __syncthreads();
            const int s = (c + 1) & 1;
            uint4 hiA, loA, hiB, loB;
            split8(na0, na1, hiA, loA);
            split8(nb0, nb1, hiB, loB);
            *(uint4*)(&sm[s][0][soff]) = hiA;
            *(uint4*)(&sm[s][1][soff]) = loA;
            *(uint4*)(&sm[s][2][soff]) = hiB;
            *(uint4*)(&sm[s][3][soff]) = loB;
            __syncthreads();
        }
    }

    const int erow  = bm + wm * 64 + (l >> 2);
    const int ecol0 = bn + wn * 32 + 2 * (l & 3);

    float2 bv[4];
#pragma unroll
    for (int ni = 0; ni < 4; ni++) {
        if (bias) {
            bv[ni].x = bias[ecol0 + ni * 8];
            bv[ni].y = bias[ecol0 + ni * 8 + 1];
        } else {
            bv[ni].x = 0.f; bv[ni].y = 0.f;
        }
    }

#pragma unroll
    for (int mi = 0; mi < 4; mi++) {
#pragma unroll
        for (int ni = 0; ni < 4; ni++) {
            const int r = erow + mi * 16;
            float2 v0, v1;
            v0.x = acc[mi][ni][0] + bv[ni].x;
            v0.y = acc[mi][ni][1] + bv[ni].y;
            v1.x = acc[mi][ni][2] + bv[ni].x;
            v1.y = acc[mi][ni][3] + bv[ni].y;
            if (EPI == 1) {
                v0.x = 1.f / (1.f + expf(-v0.x));
                v0.y = 1.f / (1.f + expf(-v0.y));
                v1.x = 1.f / (1.f + expf(-v1.x));
                v1.y = 1.f / (1.f + expf(-v1.y));
            }
            *(float2*)(C + (size_t)r * GN + ecol0 + ni * 8)       = v0;
            *(float2*)(C + (size_t)(r + 8) * GN + ecol0 + ni * 8) = v1;
        }
    }
}

// ---------------------------------------------------------------------------
// Fragment-layout scan. 128 CTAs x 256 threads (8 warps).
// Warp w: chunks j = 8w..8w+7 (k in [128w,128w+128)); A-matrix B-fragments
// stationary in regs. State loaded as fragments: one LDG.64 per chunk per
// lane from each of hi/lo arrays (contiguous 256B per warp per chunk).
// Only sync in the step: 1 __syncthreads + counter barrier.
// ---------------------------------------------------------------------------
__global__ __launch_bounds__(256, 1)
void scan_frag(const float* __restrict__ A)
{
    __shared__ float RED[8 * 64];

    const int tid = threadIdx.x;
    const int w   = tid >> 5;
    const int l   = tid & 31;
    const int bid = blockIdx.x;
    const int eBase = bid * EPER;
    const int J     = eBase >> 4;          // chunk this CTA's outputs live in
    const int h_own = (eBase >> 3) & 1;    // which k-half of that chunk

    // --- stationary B fragments: B[k][n] = Amat[eBase+n][k]
    uint32_t uH[8][2], uL[8][2];
    {
        const int e_row = eBase + (l >> 2);
#pragma unroll
        for (int jj = 0; jj < 8; jj++) {
#pragma unroll
            for (int r = 0; r < 2; r++) {
                int k = 128 * w + 16 * jj + 2 * (l & 3) + 8 * r;
                float2 av = *(const float2*)(A + (size_t)e_row * DIMD + k);
                uH[jj][r] = hipack(av.x, av.y);
                uL[jj][r] = lopack(av.x, av.y);
            }
        }
    }

    // --- producer mapping: thread tid<32 owns (b = tid>>2, c = tid&3),
    //     i.e. output dims e = eBase + 2c, eBase + 2c + 1
    const int pb = tid >> 2, pc = tid & 3;
    const uint32_t Wd = (uint32_t)(J * 64 + pb * 8 + pc * 2 + h_own);

    float u0 = 0.f, u1 = 0.f, gg0 = 0.f, gg1 = 0.f, i0 = 0.f, i1 = 0.f;
    if (tid < 32) {
        size_t idx = ((size_t)pb * SEQ) * DIMD + (size_t)(eBase + 2 * pc);
        float2 uu = *(const float2*)(g_u + idx);
        float2 gv = *(const float2*)(g_gate + idx);
        float2 iv = *(const float2*)(g_inp + idx);
        u0 = uu.x; u1 = uu.y; gg0 = gv.x; gg1 = gv.y; i0 = iv.x; i1 = iv.y;
    }

    for (int t = 0; t < SEQ; t++) {
        // 1) per-warp poll: state(t) complete when counter >= 128*t
        if (l == 0) {
            const unsigned target = (unsigned)(NSCAN) * (unsigned)t;
            while (ld_acquire(&g_counter) < target) { }
        }
        __syncwarp();

        // 2) fragment loads (8 chunks x hi/lo), then 24 MMAs
        const uint32_t* fh = g_fh[t & 1];
        const uint32_t* fl = g_fl[t & 1];
        uint2 ph[8], pl[8];
#pragma unroll
        for (int jj = 0; jj < 8; jj++) {
            const uint32_t woff = (uint32_t)((8 * w + jj) * 64 + l * 2);
            ph[jj] = ldcg2(fh + woff);
            pl[jj] = ldcg2(fl + woff);
        }

        float acc[4] = {0.f, 0.f, 0.f, 0.f};
#pragma unroll
        for (int jj = 0; jj < 8; jj++) {
            MMAZ(acc, ph[jj].x, ph[jj].y, uH[jj]);
            MMAZ(acc, ph[jj].x, ph[jj].y, uL[jj]);
            MMAZ(acc, pl[jj].x, pl[jj].y, uH[jj]);
        }

        // 3) partials -> SMEM (lane holds (b=l>>2, e-pair 2(l&3)))
        *(float2*)&RED[w * 64 + (l >> 2) * 8 + 2 * (l & 3)] =
            make_float2(acc[0], acc[1]);
        __syncthreads();

        // 4) epilogue: warp 0, thread owns 2 outputs
        if (tid < 32) {
            float y0 = 0.f, y1 = 0.f;
#pragma unroll
            for (int ww = 0; ww < 8; ww++) {
                float2 v = *(const float2*)&RED[ww * 64 + pb * 8 + 2 * pc];
                y0 += v.x; y1 += v.y;
            }

            float sv0 = tanhf(y0 + u0);
            sv0 = gg0 * sv0 + (1.f - gg0) * i0;
            float sv1 = tanhf(y1 + u1);
            sv1 = gg1 * sv1 + (1.f - gg1) * i1;

            // fp32 states for the output GEMM (off critical path)
            *(float2*)(g_states + ((size_t)pb * SEQ + t) * DIMD + eBase + 2 * pc) =
                make_float2(sv0, sv1);

            // next-state fragment words
            g_fh[(t + 1) & 1][Wd] = hipack(sv0, sv1);
            g_fl[(t + 1) & 1][Wd] = lopack(sv0, sv1);

            // prefetch next step's epilogue operands
            if (t + 1 < SEQ) {
                size_t idx = ((size_t)pb * SEQ + (t + 1)) * DIMD + (size_t)(eBase + 2 * pc);
                float2 uu = *(const float2*)(g_u + idx);
                float2 gv = *(const float2*)(g_gate + idx);
                float2 iv = *(const float2*)(g_inp + idx);
                u0 = uu.x; u1 = uu.y; gg0 = gv.x; gg1 = gv.y; i0 = iv.x; i1 = iv.y;
            }

            __syncwarp();
            if (tid == 0) red_release_add1(&g_counter);
        }
        // warps 1-7 proceed straight to the next poll
    }
}

// ---------------------------------------------------------------------------
// kernel_launch
// ---------------------------------------------------------------------------
extern "C" void kernel_launch(void* const* d_in, const int* in_sizes, int n_in,
                              void* d_out, int out_size)
{
    (void)in_sizes; (void)n_in; (void)out_size;

    const float* x      = (const float*)d_in[0];
    const float* A      = (const float*)d_in[1];
    const float* Bmat   = (const float*)d_in[2];
    const float* W_in   = (const float*)d_in[3];
    const float* b_in   = (const float*)d_in[4];
    const float* W_gate = (const float*)d_in[5];
    const float* b_gate = (const float*)d_in[6];
    const float* W_out  = (const float*)d_in[7];
    const float* b_out  = (const float*)d_in[8];
    float* out          = (float*)d_out;

    void *p_inp, *p_gate, *p_u, *p_states;
    cudaGetSymbolAddress(&p_inp,    g_inp);
    cudaGetSymbolAddress(&p_gate,   g_gate);
    cudaGetSymbolAddress(&p_u,      g_u);
    cudaGetSymbolAddress(&p_states, g_states);

    float* inp    = (float*)p_inp;
    float* gate   = (float*)p_gate;
    float* u      = (float*)p_u;
    float* states = (float*)p_states;

    init_kernel<<<(64 * 64 + 255) / 256, 256>>>();

    dim3 gg(DIMD / 128, MTOT / 128);   // (8, 256)

    gemm_mma<0><<<gg, 256>>>(x, W_in, b_in, inp);
    gemm_mma<1><<<gg, 256>>>(inp, W_gate, b_gate, gate);
    gemm_mma<0><<<gg, 256>>>(inp, Bmat, nullptr, u);
    scan_frag<<<NSCAN, 256>>>(A);
    gemm_mma<0><<<gg, 256>>>(states, W_out, b_out, out);
}

// round 9
// speedup vs baseline: 1.2717x; 1.1550x over previous
#include <cuda_runtime.h>
#include <math.h>
#include <stdint.h>

// ---------------------------------------------------------------------------
// Problem constants
// ---------------------------------------------------------------------------
#define DIMD  1024
#define BATCH 8
#define SEQ   4096
#define MTOT  (BATCH * SEQ)
#define NSCAN 128
#define EPER  (DIMD / NSCAN)   // 8

// ---------------------------------------------------------------------------
// Scratch (device-global; no allocation allowed)
// ---------------------------------------------------------------------------
__device__ float    g_inp   [(size_t)MTOT * DIMD];
__device__ float    g_gate  [(size_t)MTOT * DIMD];
__device__ float    g_u     [(size_t)MTOT * DIMD];
__device__ float    g_states[(size_t)MTOT * DIMD];
__device__ uint32_t g_sp[2][BATCH * DIMD];   // packed state (bf16 hi | bf16 lo<<16)
__device__ unsigned g_flags[NSCAN * 32];     // per-CTA arrival flags, 128B apart

// ---------------------------------------------------------------------------
// Helpers
// ---------------------------------------------------------------------------
__device__ __forceinline__ uint32_t smem_u32(const void* p) {
    uint32_t a;
    asm("{ .reg .u64 t; cvta.to.shared.u64 t, %1; cvt.u32.u64 %0, t; }" : "=r"(a) : "l"(p));
    return a;
}

#define LDSM4(r, addr)                                                        \
    asm volatile("ldmatrix.sync.aligned.m8n8.x4.shared.b16 {%0,%1,%2,%3}, [%4];" \
        : "=r"((r)[0]), "=r"((r)[1]), "=r"((r)[2]), "=r"((r)[3]) : "r"(addr))

#define MMA16816(d, a, b)                                                     \
    asm volatile("mma.sync.aligned.m16n8k16.row.col.f32.bf16.bf16.f32 "       \
        "{%0,%1,%2,%3}, {%4,%5,%6,%7}, {%8,%9}, {%0,%1,%2,%3};"               \
        : "+f"((d)[0]), "+f"((d)[1]), "+f"((d)[2]), "+f"((d)[3])              \
        : "r"((a)[0]), "r"((a)[1]), "r"((a)[2]), "r"((a)[3]),                 \
          "r"((b)[0]), "r"((b)[1]))

__device__ __forceinline__ uint32_t hipack(float x0, float x1) {
    return __byte_perm(__float_as_uint(x0), __float_as_uint(x1), 0x7632);
}
__device__ __forceinline__ uint32_t lopack(float x0, float x1) {
    float t0 = __uint_as_float(__float_as_uint(x0) & 0xFFFF0000u);
    float t1 = __uint_as_float(__float_as_uint(x1) & 0xFFFF0000u);
    float r0 = x0 - t0, r1 = x1 - t1;
    uint32_t d;
    asm("cvt.rn.bf16x2.f32 %0, %1, %2;" : "=r"(d) : "f"(r1), "f"(r0));
    return d;
}
__device__ __forceinline__ void split8(const float4& a, const float4& b,
                                       uint4& hi, uint4& lo) {
    hi.x = hipack(a.x, a.y); hi.y = hipack(a.z, a.w);
    hi.z = hipack(b.x, b.y); hi.w = hipack(b.z, b.w);
    lo.x = lopack(a.x, a.y); lo.y = lopack(a.z, a.w);
    lo.z = lopack(b.x, b.y); lo.w = lopack(b.z, b.w);
}

__device__ __forceinline__ uint32_t swz(int row, int half) {
    return (uint32_t)(row * 32 + ((half ^ ((row >> 2) & 1)) << 4));
}

__device__ __forceinline__ uint4 ldcg4(const uint4* p) {
    uint4 v;
    asm volatile("ld.global.cg.v4.u32 {%0,%1,%2,%3}, [%4];"
                 : "=r"(v.x), "=r"(v.y), "=r"(v.z), "=r"(v.w) : "l"(p));
    return v;
}
__device__ __forceinline__ void st_release(unsigned* p, unsigned v) {
    asm volatile("st.release.gpu.global.u32 [%0], %1;" :: "l"(p), "r"(v) : "memory");
}
__device__ __forceinline__ unsigned ld_acquire(const unsigned* p) {
    unsigned v;
    asm volatile("ld.acquire.gpu.global.u32 %0, [%1];" : "=r"(v) : "l"(p) : "memory");
    return v;
}

// ---------------------------------------------------------------------------
// Init kernel: zero packed state + flags (graph replay determinism)
// ---------------------------------------------------------------------------
__global__ void init_kernel() {
    int t = blockIdx.x * blockDim.x + threadIdx.x;
    if (t < BATCH * DIMD) { g_sp[0][t] = 0u; g_sp[1][t] = 0u; }
    if (t < NSCAN * 32) g_flags[t] = 0u;
}

// ---------------------------------------------------------------------------
// bf16 3x-split tensor-core GEMM (R8 version, 597us each)
// ---------------------------------------------------------------------------
#define GK 1024
#define GN 1024
#define NCHUNK (GK / 16)

template <int EPI>
__global__ __launch_bounds__(256, 2)
void gemm_mma(const float* __restrict__ X, const float* __restrict__ W,
              const float* __restrict__ bias, float* __restrict__ C)
{
    __shared__ __align__(1024) unsigned char sm[2][4][4096];

    const int tid = threadIdx.x;
    const int wid = tid >> 5, l = tid & 31;
    const int bm = blockIdx.y * 128, bn = blockIdx.x * 128;
    const int wm = wid & 1, wn = wid >> 1;

    const int srow = tid >> 1, shalf = tid & 1;
    const float* Xp = X + (size_t)(bm + srow) * GK + shalf * 8;
    const float* Wp = W + (size_t)(bn + srow) * GK + shalf * 8;
    const uint32_t soff = swz(srow, shalf);

    const int lrow = l & 15, lhalf = l >> 4;
    uint32_t offA[4], offB[2];
#pragma unroll
    for (int mi = 0; mi < 4; mi++) offA[mi] = swz(wm * 64 + mi * 16 + lrow, lhalf);
#pragma unroll
    for (int gi = 0; gi < 2; gi++) offB[gi] = swz(wn * 32 + gi * 16 + lrow, lhalf);

    const uint32_t smbase = smem_u32(&sm[0][0][0]);

    float acc[4][4][4];
#pragma unroll
    for (int mi = 0; mi < 4; mi++)
#pragma unroll
        for (int ni = 0; ni < 4; ni++)
#pragma unroll
            for (int r = 0; r < 4; r++) acc[mi][ni][r] = 0.f;

    {
        float4 a0 = *(const float4*)(Xp + 0), a1 = *(const float4*)(Xp + 4);
        float4 b0 = *(const float4*)(Wp + 0), b1 = *(const float4*)(Wp + 4);
        uint4 hiA, loA, hiB, loB;
        split8(a0, a1, hiA, loA);
        split8(b0, b1, hiB, loB);
        *(uint4*)(&sm[0][0][soff]) = hiA;
        *(uint4*)(&sm[0][1][soff]) = loA;
        *(uint4*)(&sm[0][2][soff]) = hiB;
        *(uint4*)(&sm[0][3][soff]) = loB;
    }
    __syncthreads();

    for (int c = 0; c < NCHUNK; c++) {
        float4 na0, na1, nb0, nb1;
        if (c + 1 < NCHUNK) {
            const int kc = (c + 1) * 16;
            na0 = *(const float4*)(Xp + kc);     na1 = *(const float4*)(Xp + kc + 4);
            nb0 = *(const float4*)(Wp + kc);     nb1 = *(const float4*)(Wp + kc + 4);
        }

        const uint32_t sb = smbase + (uint32_t)(c & 1) * 16384u;

        uint32_t ah[4][4], al[4][4];
#pragma unroll
        for (int mi = 0; mi < 4; mi++) {
            LDSM4(ah[mi], sb + 0 * 4096u + offA[mi]);
            LDSM4(al[mi], sb + 1 * 4096u + offA[mi]);
        }
        uint32_t bh[4][2], bl[4][2];
#pragma unroll
        for (int gi = 0; gi < 2; gi++) {
            uint32_t t[4];
            LDSM4(t, sb + 2 * 4096u + offB[gi]);
            bh[2 * gi + 0][0] = t[0]; bh[2 * gi + 0][1] = t[2];
            bh[2 * gi + 1][0] = t[1]; bh[2 * gi + 1][1] = t[3];
            LDSM4(t, sb + 3 * 4096u + offB[gi]);
            bl[2 * gi + 0][0] = t[0]; bl[2 * gi + 0][1] = t[2];
            bl[2 * gi + 1][0] = t[1]; bl[2 * gi + 1][1] = t[3];
        }

#pragma unroll
        for (int mi = 0; mi < 4; mi++)
#pragma unroll
            for (int ni = 0; ni < 4; ni++)
                MMA16816(acc[mi][ni], ah[mi], bh[ni]);
#pragma unroll
        for (int mi = 0; mi < 4; mi++)
#pragma unroll
            for (int ni = 0; ni < 4; ni++)
                MMA16816(acc[mi][ni], ah[mi], bl[ni]);
#pragma unroll
        for (int mi = 0; mi < 4; mi++)
#pragma unroll
            for (int ni = 0; ni < 4; ni++)
                MMA16816(acc[mi][ni], al[mi], bh[ni]);

        if (c + 1 < NCHUNK) {
            __syncthreads();
            const int s = (c + 1) & 1;
            uint4 hiA, loA, hiB, loB;
            split8(na0, na1, hiA, loA);
            split8(nb0, nb1, hiB, loB);
            *(uint4*)(&sm[s][0][soff]) = hiA;
            *(uint4*)(&sm[s][1][soff]) = loA;
            *(uint4*)(&sm[s][2][soff]) = hiB;
            *(uint4*)(&sm[s][3][soff]) = loB;
            __syncthreads();
        }
    }

    const int erow  = bm + wm * 64 + (l >> 2);
    const int ecol0 = bn + wn * 32 + 2 * (l & 3);

    float2 bv[4];
#pragma unroll
    for (int ni = 0; ni < 4; ni++) {
        if (bias) {
            bv[ni].x = bias[ecol0 + ni * 8];
            bv[ni].y = bias[ecol0 + ni * 8 + 1];
        } else {
            bv[ni].x = 0.f; bv[ni].y = 0.f;
        }
    }

#pragma unroll
    for (int mi = 0; mi < 4; mi++) {
#pragma unroll
        for (int ni = 0; ni < 4; ni++) {
            const int r = erow + mi * 16;
            float2 v0, v1;
            v0.x = acc[mi][ni][0] + bv[ni].x;
            v0.y = acc[mi][ni][1] + bv[ni].y;
            v1.x = acc[mi][ni][2] + bv[ni].x;
            v1.y = acc[mi][ni][3] + bv[ni].y;
            if (EPI == 1) {
                v0.x = 1.f / (1.f + expf(-v0.x));
                v0.y = 1.f / (1.f + expf(-v0.y));
                v1.x = 1.f / (1.f + expf(-v1.x));
                v1.y = 1.f / (1.f + expf(-v1.y));
            }
            *(float2*)(C + (size_t)r * GN + ecol0 + ni * 8)       = v0;
            *(float2*)(C + (size_t)(r + 8) * GN + ecol0 + ni * 8) = v1;
        }
    }
}

// ---------------------------------------------------------------------------
// R5 scan body + distributed-flag barrier.
// 128 CTAs x 256 threads, CTA owns 8 e-dims, warp w = k-seg [128w,128w+128).
// Sync per step: 128 release-flags (one line per CTA, NO atomics), threads
// 64..191 poll one flag each, one __syncthreads propagates the acquires.
// ---------------------------------------------------------------------------
#define SCAN_SMEM (32768 * 2 + 2048)

__global__ __launch_bounds__(256, 1)
void scan_mma(const float* __restrict__ A)
{
    extern __shared__ unsigned char sms[];
    unsigned char* SH = sms;                    // 16 x 2048 B (rows 8-15 zero pad)
    unsigned char* SL = sms + 32768;
    float* RED        = (float*)(sms + 65536);  // [8][64]

    const int tid = threadIdx.x;
    const int w   = tid >> 5;
    const int l   = tid & 31;
    const int bid = blockIdx.x;
    const int eBase = bid * EPER;

    const uint32_t shb = smem_u32(SH);
    const uint32_t slb = smem_u32(SL);

    // zero pad rows 8..15 once
    for (int i = tid * 16; i < 16384; i += 256 * 16) {
        *(uint4*)(SH + 16384 + i) = make_uint4(0, 0, 0, 0);
        *(uint4*)(SL + 16384 + i) = make_uint4(0, 0, 0, 0);
    }

    // --- stationary B fragments: B[k][n] = Amat[eBase+n][k], pre-split hi/lo
    uint32_t uH[8][2], uL[8][2];
    {
        const int e_row = eBase + (l >> 2);
#pragma unroll
        for (int j = 0; j < 8; j++) {
#pragma unroll
            for (int r = 0; r < 2; r++) {
                int k = 128 * w + 16 * j + 2 * (l & 3) + 8 * r;
                float2 av = *(const float2*)(A + (size_t)e_row * DIMD + k);
                uH[j][r] = hipack(av.x, av.y);
                uL[j][r] = lopack(av.x, av.y);
            }
        }
    }

    // --- ldmatrix lane geometry (A-operand, 16x16 tiles)
    const int g    = l >> 3;
    const int lrow = (g & 1) * 8 + (l & 7);
    const int lkh  = (g >> 1) & 1;
    const uint32_t lsw    = (uint32_t)((lrow & 7) << 4);
    const uint32_t cbase  = (uint32_t)(256 * w + 16 * lkh);
    const uint32_t rowoff = (uint32_t)(lrow * 2048);

    // --- epilogue mapping (threads 0..63 own one (b,e) output)
    const int b_o = tid >> 3;
    const int e_o = tid & 7;

    float u_r = 0.f, g_r = 0.f, i_r = 0.f;
    if (tid < 64) {
        size_t idx0 = (size_t)b_o * SEQ * DIMD + (size_t)(eBase + e_o);
        u_r = g_u[idx0]; g_r = g_gate[idx0]; i_r = g_inp[idx0];
    }

    // --- poller mapping: threads 64..191 poll flag of CTA (tid-64)
    const unsigned* pollp = (tid >= 64 && tid < 192) ? &g_flags[(tid - 64) * 32] : nullptr;

    // --- state fill geometry: warp w loads batch row b=w
    const uint32_t stsw = (uint32_t)((w & 7) << 4);

    __syncthreads();   // zero-pad visible

    for (int t = 0; t < SEQ; t++) {
        // 0) distributed detect: flag[i] >= t means CTA i published state(t)
        if (pollp) {
            const unsigned ut = (unsigned)t;
            while (ld_acquire(pollp) < ut) { }
        }
        __syncthreads();   // S0: propagate acquires; state(t) readable

        // 1) load packed state row b=w (L2, bypass stale L1)
        const uint4* srow = (const uint4*)(&g_sp[t & 1][w * DIMD]);
        uint4 p[8];
#pragma unroll
        for (int i = 0; i < 8; i++) p[i] = ldcg4(srow + i * 32 + l);

        // 2) unpack to swizzled SMEM tiles (hi, lo)
#pragma unroll
        for (int i = 0; i < 8; i++) {
            uint32_t h0 = __byte_perm(p[i].x, p[i].y, 0x5410);
            uint32_t h1 = __byte_perm(p[i].z, p[i].w, 0x5410);
            uint32_t q0 = __byte_perm(p[i].x, p[i].y, 0x7632);
            uint32_t q1 = __byte_perm(p[i].z, p[i].w, 0x7632);
            uint32_t cb = ((uint32_t)(256 * i + 8 * l)) ^ stsw;
            *(uint2*)(SH + w * 2048 + cb) = make_uint2(h0, h1);
            *(uint2*)(SL + w * 2048 + cb) = make_uint2(q0, q1);
        }
        __syncthreads();   // S1: tiles staged

        // 3) 8 chunks x 3 split MMAs
        float acc0[4] = {0.f, 0.f, 0.f, 0.f};
        float acc1[4] = {0.f, 0.f, 0.f, 0.f};
#pragma unroll
        for (int j = 0; j < 8; j++) {
            uint32_t cb = (cbase + 32u * j) ^ lsw;
            uint32_t ah[4], as[4];
            LDSM4(ah, shb + rowoff + cb);
            LDSM4(as, slb + rowoff + cb);
            float* acc = (j & 1) ? acc1 : acc0;
            MMA16816(acc, ah, uH[j]);
            MMA16816(acc, ah, uL[j]);
            MMA16816(acc, as, uH[j]);
        }
        float c0 = acc0[0] + acc1[0];
        float c1 = acc0[1] + acc1[1];

        // 4) cross-warp reduce partials
        *(float2*)&RED[w * 64 + (l >> 2) * 8 + 2 * (l & 3)] = make_float2(c0, c1);
        __syncthreads();   // S2: partials visible

        // 5) epilogue (warps 0-1), then named-bar + release flag
        if (tid < 64) {
            float y = 0.f;
#pragma unroll
            for (int ww = 0; ww < 8; ww++) y += RED[ww * 64 + tid];

            float sv = tanhf(y + u_r);
            sv = g_r * sv + (1.f - g_r) * i_r;

            g_states[((size_t)b_o * SEQ + t) * DIMD + eBase + e_o] = sv;

            uint32_t fui = __float_as_uint(sv);
            float resid = sv - __uint_as_float(fui & 0xFFFF0000u);
            uint32_t lo2;
            asm("cvt.rn.bf16x2.f32 %0, %1, %2;" : "=r"(lo2) : "f"(0.f), "f"(resid));
            uint32_t packed = (fui >> 16) | (lo2 << 16);
            g_sp[(t + 1) & 1][b_o * DIMD + eBase + e_o] = packed;

            if (t + 1 < SEQ) {
                size_t idx = ((size_t)b_o * SEQ + (t + 1)) * DIMD + (eBase + e_o);
                u_r = g_u[idx]; g_r = g_gate[idx]; i_r = g_inp[idx];
            }

            // order the 64 epilogue threads' STGs before the release store
            asm volatile("bar.sync 3, 64;" ::: "memory");
            if (tid == 0) st_release(&g_flags[bid * 32], (unsigned)(t + 1));
        }
        // other warps proceed straight to the next poll / S0
    }
}

// ---------------------------------------------------------------------------
// kernel_launch
// ---------------------------------------------------------------------------
extern "C" void kernel_launch(void* const* d_in, const int* in_sizes, int n_in,
                              void* d_out, int out_size)
{
    (void)in_sizes; (void)n_in; (void)out_size;

    const float* x      = (const float*)d_in[0];
    const float* A      = (const float*)d_in[1];
    const float* Bmat   = (const float*)d_in[2];
    const float* W_in   = (const float*)d_in[3];
    const float* b_in   = (const float*)d_in[4];
    const float* W_gate = (const float*)d_in[5];
    const float* b_gate = (const float*)d_in[6];
    const float* W_out  = (const float*)d_in[7];
    const float* b_out  = (const float*)d_in[8];
    float* out          = (float*)d_out;

    void *p_inp, *p_gate, *p_u, *p_states;
    cudaGetSymbolAddress(&p_inp,    g_inp);
    cudaGetSymbolAddress(&p_gate,   g_gate);
    cudaGetSymbolAddress(&p_u,      g_u);
    cudaGetSymbolAddress(&p_states, g_states);

    float* inp    = (float*)p_inp;
    float* gate   = (float*)p_gate;
    float* u      = (float*)p_u;
    float* states = (float*)p_states;

    cudaFuncSetAttribute(scan_mma, cudaFuncAttributeMaxDynamicSharedMemorySize, SCAN_SMEM);

    init_kernel<<<(BATCH * DIMD + 255) / 256, 256>>>();

    dim3 gg(DIMD / 128, MTOT / 128);   // (8, 256)

    gemm_mma<0><<<gg, 256>>>(x, W_in, b_in, inp);
    gemm_mma<1><<<gg, 256>>>(inp, W_gate, b_gate, gate);
    gemm_mma<0><<<gg, 256>>>(inp, Bmat, nullptr, u);
    scan_mma<<<NSCAN, 256, SCAN_SMEM>>>(A);
    gemm_mma<0><<<gg, 256>>>(states, W_out, b_out, out);
}

// round 10
// speedup vs baseline: 1.3279x; 1.0442x over previous
#include <cuda_runtime.h>
#include <math.h>
#include <stdint.h>

// ---------------------------------------------------------------------------
// Problem constants
// ---------------------------------------------------------------------------
#define DIMD  1024
#define BATCH 8
#define SEQ   4096
#define MTOT  (BATCH * SEQ)
#define NSCAN 128
#define EPER  (DIMD / NSCAN)   // 8

// ---------------------------------------------------------------------------
// Scratch (device-global; no allocation allowed)
// ---------------------------------------------------------------------------
__device__ float    g_inp [(size_t)MTOT * DIMD];
__device__ float    g_gate[(size_t)MTOT * DIMD];
__device__ float    g_u   [(size_t)MTOT * DIMD];
// pre-split bf16 operands (hi = truncation, lo = rn(residual))
__device__ unsigned short g_xh[(size_t)MTOT * DIMD];
__device__ unsigned short g_xl[(size_t)MTOT * DIMD];
__device__ unsigned short g_ih[(size_t)MTOT * DIMD];
__device__ unsigned short g_il[(size_t)MTOT * DIMD];
__device__ unsigned short g_sh[(size_t)MTOT * DIMD];
__device__ unsigned short g_sl[(size_t)MTOT * DIMD];
__device__ unsigned short g_wh[4][DIMD * DIMD];
__device__ unsigned short g_wl[4][DIMD * DIMD];
__device__ uint32_t g_sp[2][BATCH * DIMD];   // packed scan state (bf16hi | bf16lo<<16)
__device__ unsigned g_counter;

// ---------------------------------------------------------------------------
// Helpers
// ---------------------------------------------------------------------------
__device__ __forceinline__ uint32_t smem_u32(const void* p) {
    uint32_t a;
    asm("{ .reg .u64 t; cvta.to.shared.u64 t, %1; cvt.u32.u64 %0, t; }" : "=r"(a) : "l"(p));
    return a;
}

#define LDSM4(r, addr)                                                        \
    asm volatile("ldmatrix.sync.aligned.m8n8.x4.shared.b16 {%0,%1,%2,%3}, [%4];" \
        : "=r"((r)[0]), "=r"((r)[1]), "=r"((r)[2]), "=r"((r)[3]) : "r"(addr))

#define MMA16816(d, a, b)                                                     \
    asm volatile("mma.sync.aligned.m16n8k16.row.col.f32.bf16.bf16.f32 "       \
        "{%0,%1,%2,%3}, {%4,%5,%6,%7}, {%8,%9}, {%0,%1,%2,%3};"               \
        : "+f"((d)[0]), "+f"((d)[1]), "+f"((d)[2]), "+f"((d)[3])              \
        : "r"((a)[0]), "r"((a)[1]), "r"((a)[2]), "r"((a)[3]),                 \
          "r"((b)[0]), "r"((b)[1]))

__device__ __forceinline__ uint32_t hipack(float x0, float x1) {
    return __byte_perm(__float_as_uint(x0), __float_as_uint(x1), 0x7632);
}
__device__ __forceinline__ uint32_t lopack(float x0, float x1) {
    float t0 = __uint_as_float(__float_as_uint(x0) & 0xFFFF0000u);
    float t1 = __uint_as_float(__float_as_uint(x1) & 0xFFFF0000u);
    float r0 = x0 - t0, r1 = x1 - t1;
    uint32_t d;
    asm("cvt.rn.bf16x2.f32 %0, %1, %2;" : "=r"(d) : "f"(r1), "f"(r0));
    return d;
}

__device__ __forceinline__ uint32_t swz(int row, int half) {
    return (uint32_t)(row * 32 + ((half ^ ((row >> 2) & 1)) << 4));
}

__device__ __forceinline__ uint4 ldcg4(const uint4* p) {
    uint4 v;
    asm volatile("ld.global.cg.v4.u32 {%0,%1,%2,%3}, [%4];"
                 : "=r"(v.x), "=r"(v.y), "=r"(v.z), "=r"(v.w) : "l"(p));
    return v;
}
__device__ __forceinline__ void red_release_add1(unsigned* p) {
    asm volatile("red.release.gpu.global.add.u32 [%0], 1;" :: "l"(p) : "memory");
}
__device__ __forceinline__ unsigned ld_acquire(const unsigned* p) {
    unsigned v;
    asm volatile("ld.acquire.gpu.global.u32 %0, [%1];" : "=r"(v) : "l"(p) : "memory");
    return v;
}

// ---------------------------------------------------------------------------
// Init kernel
// ---------------------------------------------------------------------------
__global__ void init_kernel() {
    int t = blockIdx.x * blockDim.x + threadIdx.x;
    if (t < BATCH * DIMD) { g_sp[0][t] = 0u; g_sp[1][t] = 0u; }
    if (t == 0) g_counter = 0u;
}

// ---------------------------------------------------------------------------
// Elementwise fp32 -> (hi, lo) bf16 split, 4 elems/thread
// ---------------------------------------------------------------------------
__global__ void split_kernel(const float4* __restrict__ X,
                             uint2* __restrict__ H, uint2* __restrict__ L, int n4)
{
    int i = blockIdx.x * blockDim.x + threadIdx.x;
    if (i < n4) {
        float4 v = X[i];
        uint2 h, l;
        h.x = hipack(v.x, v.y); h.y = hipack(v.z, v.w);
        l.x = lopack(v.x, v.y); l.y = lopack(v.z, v.w);
        H[i] = h; L[i] = l;
    }
}

// ---------------------------------------------------------------------------
// bf16-input 3x-split tensor-core GEMM (NT).
// Same tiling as before, but operands arrive PRE-SPLIT: no in-loop CVT/LOP.
// EPI: 0 none, 1 sigmoid. WSPLIT: also emit hi/lo bf16 of the fp32 result.
// ---------------------------------------------------------------------------
#define GK 1024
#define GN 1024
#define NCHUNK (GK / 16)

template <int EPI, int WSPLIT>
__global__ __launch_bounds__(256, 2)
void gemm_bf16(const unsigned short* __restrict__ Xh, const unsigned short* __restrict__ Xl,
               const unsigned short* __restrict__ Wh, const unsigned short* __restrict__ Wl,
               const float* __restrict__ bias, float* __restrict__ C,
               unsigned short* __restrict__ Ch, unsigned short* __restrict__ Cl)
{
    __shared__ __align__(1024) unsigned char sm[2][4][4096];

    const int tid = threadIdx.x;
    const int wid = tid >> 5, l = tid & 31;
    const int bm = blockIdx.y * 128, bn = blockIdx.x * 128;
    const int wm = wid & 1, wn = wid >> 1;

    const int srow = tid >> 1, shalf = tid & 1;
    const unsigned short* Xph = Xh + (size_t)(bm + srow) * GK + shalf * 8;
    const unsigned short* Xpl = Xl + (size_t)(bm + srow) * GK + shalf * 8;
    const unsigned short* Wph = Wh + (size_t)(bn + srow) * GK + shalf * 8;
    const unsigned short* Wpl = Wl + (size_t)(bn + srow) * GK + shalf * 8;
    const uint32_t soff = swz(srow, shalf);

    const int lrow = l & 15, lhalf = l >> 4;
    uint32_t offA[4], offB[2];
#pragma unroll
    for (int mi = 0; mi < 4; mi++) offA[mi] = swz(wm * 64 + mi * 16 + lrow, lhalf);
#pragma unroll
    for (int gi = 0; gi < 2; gi++) offB[gi] = swz(wn * 32 + gi * 16 + lrow, lhalf);

    float acc[4][4][4];
#pragma unroll
    for (int mi = 0; mi < 4; mi++)
#pragma unroll
        for (int ni = 0; ni < 4; ni++)
#pragma unroll
            for (int r = 0; r < 4; r++) acc[mi][ni][r] = 0.f;

    {
        uint4 ah = *(const uint4*)(Xph);
        uint4 al = *(const uint4*)(Xpl);
        uint4 bh = *(const uint4*)(Wph);
        uint4 bl = *(const uint4*)(Wpl);
        *(uint4*)(&sm[0][0][soff]) = ah;
        *(uint4*)(&sm[0][1][soff]) = al;
        *(uint4*)(&sm[0][2][soff]) = bh;
        *(uint4*)(&sm[0][3][soff]) = bl;
    }
    __syncthreads();

    const uint32_t smbase = smem_u32(&sm[0][0][0]);

    for (int c = 0; c < NCHUNK; c++) {
        uint4 nah, nal, nbh, nbl;
        if (c + 1 < NCHUNK) {
            const int kc = (c + 1) * 16;
            nah = *(const uint4*)(Xph + kc);
            nal = *(const uint4*)(Xpl + kc);
            nbh = *(const uint4*)(Wph + kc);
            nbl = *(const uint4*)(Wpl + kc);
        }

        const uint32_t sb = smbase + (uint32_t)(c & 1) * 16384u;

        uint32_t ah[4][4], al[4][4];
#pragma unroll
        for (int mi = 0; mi < 4; mi++) {
            LDSM4(ah[mi], sb + 0 * 4096u + offA[mi]);
            LDSM4(al[mi], sb + 1 * 4096u + offA[mi]);
        }
        uint32_t bh[4][2], bl[4][2];
#pragma unroll
        for (int gi = 0; gi < 2; gi++) {
            uint32_t t[4];
            LDSM4(t, sb + 2 * 4096u + offB[gi]);
            bh[2 * gi + 0][0] = t[0]; bh[2 * gi + 0][1] = t[2];
            bh[2 * gi + 1][0] = t[1]; bh[2 * gi + 1][1] = t[3];
            LDSM4(t, sb + 3 * 4096u + offB[gi]);
            bl[2 * gi + 0][0] = t[0]; bl[2 * gi + 0][1] = t[2];
            bl[2 * gi + 1][0] = t[1]; bl[2 * gi + 1][1] = t[3];
        }

#pragma unroll
        for (int mi = 0; mi < 4; mi++)
#pragma unroll
            for (int ni = 0; ni < 4; ni++)
                MMA16816(acc[mi][ni], ah[mi], bh[ni]);
#pragma unroll
        for (int mi = 0; mi < 4; mi++)
#pragma unroll
            for (int ni = 0; ni < 4; ni++)
                MMA16816(acc[mi][ni], ah[mi], bl[ni]);
#pragma unroll
        for (int mi = 0; mi < 4; mi++)
#pragma unroll
            for (int ni = 0; ni < 4; ni++)
                MMA16816(acc[mi][ni], al[mi], bh[ni]);

        if (c + 1 < NCHUNK) {
            __syncthreads();
            const int s = (c + 1) & 1;
            *(uint4*)(&sm[s][0][soff]) = nah;
            *(uint4*)(&sm[s][1][soff]) = nal;
            *(uint4*)(&sm[s][2][soff]) = nbh;
            *(uint4*)(&sm[s][3][soff]) = nbl;
            __syncthreads();
        }
    }

    const int erow  = bm + wm * 64 + (l >> 2);
    const int ecol0 = bn + wn * 32 + 2 * (l & 3);

    float2 bv[4];
#pragma unroll
    for (int ni = 0; ni < 4; ni++) {
        if (bias) {
            bv[ni].x = bias[ecol0 + ni * 8];
            bv[ni].y = bias[ecol0 + ni * 8 + 1];
        } else {
            bv[ni].x = 0.f; bv[ni].y = 0.f;
        }
    }

#pragma unroll
    for (int mi = 0; mi < 4; mi++) {
#pragma unroll
        for (int ni = 0; ni < 4; ni++) {
            const int r = erow + mi * 16;
            float2 v0, v1;
            v0.x = acc[mi][ni][0] + bv[ni].x;
            v0.y = acc[mi][ni][1] + bv[ni].y;
            v1.x = acc[mi][ni][2] + bv[ni].x;
            v1.y = acc[mi][ni][3] + bv[ni].y;
            if (EPI == 1) {
                v0.x = 1.f / (1.f + expf(-v0.x));
                v0.y = 1.f / (1.f + expf(-v0.y));
                v1.x = 1.f / (1.f + expf(-v1.x));
                v1.y = 1.f / (1.f + expf(-v1.y));
            }
            *(float2*)(C + (size_t)r * GN + ecol0 + ni * 8)       = v0;
            *(float2*)(C + (size_t)(r + 8) * GN + ecol0 + ni * 8) = v1;
            if (WSPLIT) {
                *(uint32_t*)(Ch + (size_t)r * GN + ecol0 + ni * 8)       = hipack(v0.x, v0.y);
                *(uint32_t*)(Cl + (size_t)r * GN + ecol0 + ni * 8)       = lopack(v0.x, v0.y);
                *(uint32_t*)(Ch + (size_t)(r + 8) * GN + ecol0 + ni * 8) = hipack(v1.x, v1.y);
                *(uint32_t*)(Cl + (size_t)(r + 8) * GN + ecol0 + ni * 8) = lopack(v1.x, v1.y);
            }
        }
    }
}

// ---------------------------------------------------------------------------
// Scan: exact R5 body (best measured), states emitted pre-split hi/lo bf16.
// 128 CTAs x 256 threads, CTA owns 8 e-dims, warp w = k-seg [128w,128w+128).
// ---------------------------------------------------------------------------
#define SCAN_SMEM (32768 * 2 + 2048)

__global__ __launch_bounds__(256, 1)
void scan_mma(const float* __restrict__ A)
{
    extern __shared__ unsigned char sms[];
    unsigned char* SH = sms;                    // 16 x 2048 B (rows 8-15 zero pad)
    unsigned char* SL = sms + 32768;
    float* RED        = (float*)(sms + 65536);  // [8][64]

    const int tid = threadIdx.x;
    const int w   = tid >> 5;
    const int l   = tid & 31;
    const int eBase = blockIdx.x * EPER;

    const uint32_t shb = smem_u32(SH);
    const uint32_t slb = smem_u32(SL);

    for (int i = tid * 16; i < 16384; i += 256 * 16) {
        *(uint4*)(SH + 16384 + i) = make_uint4(0, 0, 0, 0);
        *(uint4*)(SL + 16384 + i) = make_uint4(0, 0, 0, 0);
    }

    uint32_t uH[8][2], uL[8][2];
    {
        const int e_row = eBase + (l >> 2);
#pragma unroll
        for (int j = 0; j < 8; j++) {
#pragma unroll
            for (int r = 0; r < 2; r++) {
                int k = 128 * w + 16 * j + 2 * (l & 3) + 8 * r;
                float2 av = *(const float2*)(A + (size_t)e_row * DIMD + k);
                uH[j][r] = hipack(av.x, av.y);
                uL[j][r] = lopack(av.x, av.y);
            }
        }
    }

    const int g    = l >> 3;
    const int lrow = (g & 1) * 8 + (l & 7);
    const int lkh  = (g >> 1) & 1;
    const uint32_t lsw    = (uint32_t)((lrow & 7) << 4);
    const uint32_t cbase  = (uint32_t)(256 * w + 16 * lkh);
    const uint32_t rowoff = (uint32_t)(lrow * 2048);

    const int b_o = tid >> 3;
    const int e_o = tid & 7;

    float u_r = 0.f, g_r = 0.f, i_r = 0.f;
    if (tid < 64) {
        size_t idx0 = (size_t)b_o * SEQ * DIMD + (size_t)(eBase + e_o);
        u_r = g_u[idx0]; g_r = g_gate[idx0]; i_r = g_inp[idx0];
    }

    const uint32_t stsw = (uint32_t)((w & 7) << 4);

    __syncthreads();

    for (int t = 0; t < SEQ; t++) {
        const uint4* srow = (const uint4*)(&g_sp[t & 1][w * DIMD]);
        uint4 p[8];
#pragma unroll
        for (int i = 0; i < 8; i++) p[i] = ldcg4(srow + i * 32 + l);

#pragma unroll
        for (int i = 0; i < 8; i++) {
            uint32_t h0 = __byte_perm(p[i].x, p[i].y, 0x5410);
            uint32_t h1 = __byte_perm(p[i].z, p[i].w, 0x5410);
            uint32_t q0 = __byte_perm(p[i].x, p[i].y, 0x7632);
            uint32_t q1 = __byte_perm(p[i].z, p[i].w, 0x7632);
            uint32_t cb = ((uint32_t)(256 * i + 8 * l)) ^ stsw;
            *(uint2*)(SH + w * 2048 + cb) = make_uint2(h0, h1);
            *(uint2*)(SL + w * 2048 + cb) = make_uint2(q0, q1);
        }
        __syncthreads();

        float acc0[4] = {0.f, 0.f, 0.f, 0.f};
        float acc1[4] = {0.f, 0.f, 0.f, 0.f};
#pragma unroll
        for (int j = 0; j < 8; j++) {
            uint32_t cb = (cbase + 32u * j) ^ lsw;
            uint32_t ah[4], as[4];
            LDSM4(ah, shb + rowoff + cb);
            LDSM4(as, slb + rowoff + cb);
            float* acc = (j & 1) ? acc1 : acc0;
            MMA16816(acc, ah, uH[j]);
            MMA16816(acc, ah, uL[j]);
            MMA16816(acc, as, uH[j]);
        }
        float c0 = acc0[0] + acc1[0];
        float c1 = acc0[1] + acc1[1];

        *(float2*)&RED[w * 64 + (l >> 2) * 8 + 2 * (l & 3)] = make_float2(c0, c1);
        __syncthreads();

        if (tid < 64) {
            float y = 0.f;
#pragma unroll
            for (int ww = 0; ww < 8; ww++) y += RED[ww * 64 + tid];

            float sv = tanhf(y + u_r);
            sv = g_r * sv + (1.f - g_r) * i_r;

            uint32_t fui = __float_as_uint(sv);
            float resid = sv - __uint_as_float(fui & 0xFFFF0000u);
            uint32_t lo2;
            asm("cvt.rn.bf16x2.f32 %0, %1, %2;" : "=r"(lo2) : "f"(0.f), "f"(resid));

            // states, pre-split for the output GEMM (same hi/lo definitions)
            size_t sidx = ((size_t)b_o * SEQ + t) * DIMD + eBase + e_o;
            g_sh[sidx] = (unsigned short)(fui >> 16);
            g_sl[sidx] = (unsigned short)(lo2 & 0xFFFFu);

            uint32_t packed = (fui >> 16) | (lo2 << 16);
            g_sp[(t + 1) & 1][b_o * DIMD + eBase + e_o] = packed;

            if (t + 1 < SEQ) {
                size_t idx = ((size_t)b_o * SEQ + (t + 1)) * DIMD + (eBase + e_o);
                u_r = g_u[idx]; g_r = g_gate[idx]; i_r = g_inp[idx];
            }
        }

        __syncthreads();
        if (tid == 0) {
            red_release_add1(&g_counter);
            const unsigned target = (unsigned)NSCAN * (unsigned)(t + 1);
            while (ld_acquire(&g_counter) < target) { }
        }
        __syncthreads();
    }
}

// ---------------------------------------------------------------------------
// kernel_launch
// ---------------------------------------------------------------------------
extern "C" void kernel_launch(void* const* d_in, const int* in_sizes, int n_in,
                              void* d_out, int out_size)
{
    (void)in_sizes; (void)n_in; (void)out_size;

    const float* x      = (const float*)d_in[0];
    const float* A      = (const float*)d_in[1];
    const float* Bmat   = (const float*)d_in[2];
    const float* W_in   = (const float*)d_in[3];
    const float* b_in   = (const float*)d_in[4];
    const float* W_gate = (const float*)d_in[5];
    const float* b_gate = (const float*)d_in[6];
    const float* W_out  = (const float*)d_in[7];
    const float* b_out  = (const float*)d_in[8];
    float* out          = (float*)d_out;

    void *p_inp, *p_gate, *p_u;
    void *p_xh, *p_xl, *p_ih, *p_il, *p_sh, *p_sl, *p_wh, *p_wl;
    cudaGetSymbolAddress(&p_inp, g_inp);
    cudaGetSymbolAddress(&p_gate, g_gate);
    cudaGetSymbolAddress(&p_u, g_u);
    cudaGetSymbolAddress(&p_xh, g_xh);
    cudaGetSymbolAddress(&p_xl, g_xl);
    cudaGetSymbolAddress(&p_ih, g_ih);
    cudaGetSymbolAddress(&p_il, g_il);
    cudaGetSymbolAddress(&p_sh, g_sh);
    cudaGetSymbolAddress(&p_sl, g_sl);
    cudaGetSymbolAddress(&p_wh, g_wh);
    cudaGetSymbolAddress(&p_wl, g_wl);

    float* inp  = (float*)p_inp;
    float* gate = (float*)p_gate;
    float* u    = (float*)p_u;
    unsigned short* xh = (unsigned short*)p_xh;
    unsigned short* xl = (unsigned short*)p_xl;
    unsigned short* ih = (unsigned short*)p_ih;
    unsigned short* il = (unsigned short*)p_il;
    unsigned short* sh = (unsigned short*)p_sh;
    unsigned short* sl = (unsigned short*)p_sl;
    unsigned short* wh = (unsigned short*)p_wh;
    unsigned short* wl = (unsigned short*)p_wl;

    cudaFuncSetAttribute(scan_mma, cudaFuncAttributeMaxDynamicSharedMemorySize, SCAN_SMEM);

    init_kernel<<<(BATCH * DIMD + 255) / 256, 256>>>();

    // pre-split x and weights
    {
        const int n4x = MTOT * DIMD / 4;
        split_kernel<<<(n4x + 255) / 256, 256>>>((const float4*)x,
            (uint2*)xh, (uint2*)xl, n4x);
        const int n4w = DIMD * DIMD / 4;
        const float* Ws[4] = {W_in, W_gate, Bmat, W_out};
        for (int i = 0; i < 4; i++)
            split_kernel<<<(n4w + 255) / 256, 256>>>((const float4*)Ws[i],
                (uint2*)(wh + (size_t)i * DIMD * DIMD),
                (uint2*)(wl + (size_t)i * DIMD * DIMD), n4w);
    }

    dim3 gg(DIMD / 128, MTOT / 128);   // (8, 256)

    // 1) inp = x @ W_in^T + b_in   (also emit split inp)
    gemm_bf16<0, 1><<<gg, 256>>>(xh, xl,
        wh + 0 * (size_t)DIMD * DIMD, wl + 0 * (size_t)DIMD * DIMD,
        b_in, inp, ih, il);
    // 2) gate = sigmoid(inp @ W_gate^T + b_gate)
    gemm_bf16<1, 0><<<gg, 256>>>(ih, il,
        wh + 1 * (size_t)DIMD * DIMD, wl + 1 * (size_t)DIMD * DIMD,
        b_gate, gate, nullptr, nullptr);
    // 3) u = inp @ B^T
    gemm_bf16<0, 0><<<gg, 256>>>(ih, il,
        wh + 2 * (size_t)DIMD * DIMD, wl + 2 * (size_t)DIMD * DIMD,
        nullptr, u, nullptr, nullptr);
    // 4) scan (emits split states)
    scan_mma<<<NSCAN, 256, SCAN_SMEM>>>(A);
    // 5) out = states @ W_out^T + b_out
    gemm_bf16<0, 0><<<gg, 256>>>(sh, sl,
        wh + 3 * (size_t)DIMD * DIMD, wl + 3 * (size_t)DIMD * DIMD,
        b_out, out, nullptr, nullptr);
}